// round 1
// baseline (speedup 1.0000x reference)
#include <cuda_runtime.h>
#include <cuda_bf16.h>
#include <math.h>

#define NN    20000
#define IN_F  256
#define H     128
#define HN    4
#define S     5
#define KM    2
#define Bq    1024
#define M     16
#define D     512
#define ALPHA 0.2f
#define BM_   (Bq*M)      /* 16384 */
#define R_    (BM_ + Bq)  /* 17408 */
#define PAIRS (S*HN)      /* 20 */

__constant__ int c_kofs[S] = {0,0,1,1,1};

// ---------------- scratch (device globals; no allocations allowed) ----------------
__device__ float g_ckw[PAIRS*H*H];
__device__ float g_ckb[PAIRS*H];
__device__ float g_cqw[PAIRS*H*H];
__device__ float g_cqb[PAIRS*H];
__device__ float g_xsh[PAIRS*Bq*H];
__device__ float g_ysh[PAIRS*BM_*H];
__device__ float g_h1 [PAIRS*BM_*H];
__device__ float g_vh [PAIRS*BM_*H];
__device__ float g_h2 [PAIRS*Bq*H];
__device__ float g_wh2[PAIRS*Bq*H];
__device__ float g_sout[S*Bq*D];
__device__ float g_mp[Bq*KM*D];

// ---------------- combined weights: cw = a @ w, cb = a @ wb + ab ----------------
// cw[o,i] = sum_j a[kz][o,j] * w[z][j,i]
__global__ void combine_w(const float* __restrict__ aw, const float* __restrict__ ab,
                          const float* __restrict__ w,  const float* __restrict__ wb,
                          float* __restrict__ cw, float* __restrict__ cb)
{
    int o = blockIdx.x, z = blockIdx.y, tid = threadIdx.x;
    int s = z / HN, h = z % HN;
    int kz = c_kofs[s]*HN + h;
    const float* arow = aw + ((size_t)kz*H + o)*H;
    const float* wm   = w  + (size_t)z*H*H;
    __shared__ float sa[H];
    sa[tid] = arow[tid];
    __syncthreads();
    float acc = 0.f;
    #pragma unroll 8
    for (int j = 0; j < H; ++j) acc += sa[j]*wm[j*H + tid];
    cw[((size_t)z*H + o)*H + tid] = acc;
    if (tid == 0) {
        float bacc = ab[kz*H + o];
        const float* kb = wb + z*H;
        for (int j = 0; j < H; ++j) bacc += sa[j]*kb[j];
        cb[z*H + o] = bacc;
    }
}

// ---------------- fc GEMM with gather: C = lrelu(A[rows] @ Wt + b) ----------------
// A rows: r<16384 -> x[neigh[s][r]], else x[tgt[r-16384]]. N = 512 (4 tiles of 128 = heads)
__global__ __launch_bounds__(256) void fc_gemm(
    const float* __restrict__ x, const int* __restrict__ neigh,
    const int* __restrict__ tgt, const float* __restrict__ fcw,
    const float* __restrict__ fcb, float* __restrict__ ysh, float* __restrict__ xsh)
{
    int mt = blockIdx.x, nt = blockIdx.y, s = blockIdx.z;
    int tid = threadIdx.x;
    __shared__ float As[8][132];
    __shared__ float Bs[8][132];
    __shared__ int rows[128];
    if (tid < 128) {
        int r = mt*128 + tid;
        rows[tid] = (r < BM_) ? neigh[s*BM_ + r] : tgt[r - BM_];
    }
    __syncthreads();
    int tx = tid & 15, ty = tid >> 4;
    int la_r = tid >> 1, la_k = (tid & 1)*4;
    float acc[8][8];
    #pragma unroll
    for (int i = 0; i < 8; ++i)
        #pragma unroll
        for (int j = 0; j < 8; ++j) acc[i][j] = 0.f;
    const float* arow = x + (size_t)rows[la_r]*IN_F + la_k;
    const float* brow = fcw + ((size_t)s*512 + nt*128 + la_r)*IN_F + la_k;
    for (int k0 = 0; k0 < IN_F; k0 += 8) {
        float4 av = *(const float4*)(arow + k0);
        float4 bv = *(const float4*)(brow + k0);
        As[la_k+0][la_r]=av.x; As[la_k+1][la_r]=av.y; As[la_k+2][la_r]=av.z; As[la_k+3][la_r]=av.w;
        Bs[la_k+0][la_r]=bv.x; Bs[la_k+1][la_r]=bv.y; Bs[la_k+2][la_r]=bv.z; Bs[la_k+3][la_r]=bv.w;
        __syncthreads();
        #pragma unroll
        for (int kk = 0; kk < 8; ++kk) {
            float4 a0 = *(const float4*)&As[kk][ty*8];
            float4 a1 = *(const float4*)&As[kk][ty*8+4];
            float4 b0 = *(const float4*)&Bs[kk][tx*8];
            float4 b1 = *(const float4*)&Bs[kk][tx*8+4];
            float ra[8] = {a0.x,a0.y,a0.z,a0.w,a1.x,a1.y,a1.z,a1.w};
            float rb[8] = {b0.x,b0.y,b0.z,b0.w,b1.x,b1.y,b1.z,b1.w};
            #pragma unroll
            for (int i = 0; i < 8; ++i)
                #pragma unroll
                for (int j = 0; j < 8; ++j) acc[i][j] += ra[i]*rb[j];
        }
        __syncthreads();
    }
    int zpair = s*HN + nt;
    #pragma unroll
    for (int i = 0; i < 8; ++i) {
        int r = mt*128 + ty*8 + i;
        #pragma unroll
        for (int j = 0; j < 8; ++j) {
            int o = tx*8 + j;
            float v = acc[i][j] + fcb[zpair*H + o];
            v = v >= 0.f ? v : ALPHA*v;
            if (r < BM_) ysh[((size_t)zpair*BM_ + r)*H + o] = v;
            else         xsh[((size_t)zpair*Bq + (r-BM_))*H + o] = v;
        }
    }
}

// ---------------- generic batched GEMM: C[z] = act(A[z] @ W[wz]^T + bias[z]) ----------------
// N = K = 128, batch over z = s*HN+h (20)
__global__ __launch_bounds__(256) void gemm128(
    const float* __restrict__ Abase, const float* __restrict__ Wbase,
    const float* __restrict__ biasBase, float* __restrict__ Cbase,
    int Mrows, int doLrelu, int wKmap)
{
    int mt = blockIdx.x, z = blockIdx.y;
    int wz = z;
    if (wKmap) wz = c_kofs[z/HN]*HN + (z % HN);
    const float* A = Abase + (size_t)z*Mrows*H;
    const float* W = Wbase + (size_t)wz*H*H;
    float*       C = Cbase + (size_t)z*Mrows*H;
    int tid = threadIdx.x;
    __shared__ float As[8][132];
    __shared__ float Bs[8][132];
    int tx = tid & 15, ty = tid >> 4;
    int la_r = tid >> 1, la_k = (tid & 1)*4;
    float acc[8][8];
    #pragma unroll
    for (int i = 0; i < 8; ++i)
        #pragma unroll
        for (int j = 0; j < 8; ++j) acc[i][j] = 0.f;
    const float* arow = A + ((size_t)mt*128 + la_r)*H + la_k;
    const float* brow = W + (size_t)la_r*H + la_k;
    for (int k0 = 0; k0 < H; k0 += 8) {
        float4 av = *(const float4*)(arow + k0);
        float4 bv = *(const float4*)(brow + k0);
        As[la_k+0][la_r]=av.x; As[la_k+1][la_r]=av.y; As[la_k+2][la_r]=av.z; As[la_k+3][la_r]=av.w;
        Bs[la_k+0][la_r]=bv.x; Bs[la_k+1][la_r]=bv.y; Bs[la_k+2][la_r]=bv.z; Bs[la_k+3][la_r]=bv.w;
        __syncthreads();
        #pragma unroll
        for (int kk = 0; kk < 8; ++kk) {
            float4 a0 = *(const float4*)&As[kk][ty*8];
            float4 a1 = *(const float4*)&As[kk][ty*8+4];
            float4 b0 = *(const float4*)&Bs[kk][tx*8];
            float4 b1 = *(const float4*)&Bs[kk][tx*8+4];
            float ra[8] = {a0.x,a0.y,a0.z,a0.w,a1.x,a1.y,a1.z,a1.w};
            float rb[8] = {b0.x,b0.y,b0.z,b0.w,b1.x,b1.y,b1.z,b1.w};
            #pragma unroll
            for (int i = 0; i < 8; ++i)
                #pragma unroll
                for (int j = 0; j < 8; ++j) acc[i][j] += ra[i]*rb[j];
        }
        __syncthreads();
    }
    float bj[8];
    #pragma unroll
    for (int j = 0; j < 8; ++j) bj[j] = biasBase ? biasBase[z*H + tx*8 + j] : 0.f;
    #pragma unroll
    for (int i = 0; i < 8; ++i) {
        int r = mt*128 + ty*8 + i;
        #pragma unroll
        for (int j = 0; j < 8; ++j) {
            int o = tx*8 + j;
            float v = acc[i][j] + bj[j];
            if (doLrelu) v = v >= 0.f ? v : ALPHA*v;
            C[(size_t)r*H + o] = v;
        }
    }
}

// ---------------- per (s,h,b): att = h1 . wh2, softmax over M, h = sum lrelu(vh*e) ----------------
__global__ __launch_bounds__(128) void attn_combine(
    const float* __restrict__ h1, const float* __restrict__ vh,
    const float* __restrict__ wh2, const float* __restrict__ xsh,
    float* __restrict__ outp)
{
    int b = blockIdx.x, sh = blockIdx.y, tid = threadIdx.x;
    const float* h1b = h1 + ((size_t)sh*BM_ + b*M)*H;
    const float* vhb = vh + ((size_t)sh*BM_ + b*M)*H;
    float w = wh2[((size_t)sh*Bq + b)*H + tid];
    __shared__ float sprod[M][H+4];
    __shared__ float satt[M];
    #pragma unroll
    for (int m = 0; m < M; ++m) sprod[m][tid] = h1b[m*H + tid]*w;
    __syncthreads();
    if (tid < M) {
        float sum = 0.f;
        for (int o = 0; o < H; ++o) sum += sprod[tid][o];
        satt[tid] = sum;
    }
    __syncthreads();
    float mx = -1e30f;
    #pragma unroll
    for (int m = 0; m < M; ++m) mx = fmaxf(mx, satt[m]);
    float es[M]; float esum = 0.f;
    #pragma unroll
    for (int m = 0; m < M; ++m) { es[m] = expf(satt[m] - mx); esum += es[m]; }
    float inv = 1.f/esum;
    float acc = 0.f;
    #pragma unroll
    for (int m = 0; m < M; ++m) {
        float t = vhb[m*H + tid]*(es[m]*inv);
        acc += (t >= 0.f) ? t : ALPHA*t;
    }
    int s = sh/HN, hh = sh%HN;
    outp[((size_t)s*Bq + b)*D + hh*H + tid] =
        0.5f*(xsh[((size_t)sh*Bq + b)*H + tid] + acc);
}

// ---------------- semantic attention (both inner & between), 4 targets / block ----------------
template<int P>
__global__ __launch_bounds__(128) void semantic(
    const float* __restrict__ zin, const float* __restrict__ p1w,
    const float* __restrict__ p1b, const float* __restrict__ p2w,
    float* __restrict__ outp, int in_pstride, int in_bstride, int out_bstride)
{
    int b0 = blockIdx.x*4, tid = threadIdx.x;
    __shared__ float zs[4][P][D];
    int tot = 4*P*D;
    for (int idx = tid; idx < tot; idx += 128) {
        int d = idx % D; int rp = idx / D; int p = rp % P; int bl = rp / P;
        zs[bl][p][d] = zin[(size_t)(b0+bl)*in_bstride + (size_t)p*in_pstride + d];
    }
    __syncthreads();
    float acc[4][P];
    #pragma unroll
    for (int bl = 0; bl < 4; ++bl)
        #pragma unroll
        for (int p = 0; p < P; ++p) acc[bl][p] = 0.f;
    const float* wrow = p1w + (size_t)tid*D;
    for (int d = 0; d < D; ++d) {
        float wv = wrow[d];
        #pragma unroll
        for (int bl = 0; bl < 4; ++bl)
            #pragma unroll
            for (int p = 0; p < P; ++p) acc[bl][p] += wv*zs[bl][p][d];
    }
    float bias = p1b[tid], p2 = p2w[tid];
    __shared__ float sred[4*P][132];
    __shared__ float ssc[4*P];
    #pragma unroll
    for (int bl = 0; bl < 4; ++bl)
        #pragma unroll
        for (int p = 0; p < P; ++p)
            sred[bl*P+p][tid] = tanhf(acc[bl][p] + bias)*p2;
    __syncthreads();
    if (tid < 4*P) {
        float s_ = 0.f;
        for (int o = 0; o < H; ++o) s_ += sred[tid][o];
        ssc[tid] = s_;
    }
    __syncthreads();
    #pragma unroll
    for (int bl = 0; bl < 4; ++bl) {
        float mx = -1e30f;
        #pragma unroll
        for (int p = 0; p < P; ++p) mx = fmaxf(mx, ssc[bl*P+p]);
        float e[P]; float esum = 0.f;
        #pragma unroll
        for (int p = 0; p < P; ++p) { e[p] = expf(ssc[bl*P+p] - mx); esum += e[p]; }
        float inv = 1.f/esum;
        for (int d = tid; d < D; d += 128) {
            float o_ = 0.f;
            #pragma unroll
            for (int p = 0; p < P; ++p) o_ += e[p]*zs[bl][p][d];
            outp[(size_t)(b0+bl)*out_bstride + d] = o_*inv;
        }
    }
}

extern "C" void kernel_launch(void* const* d_in, const int* in_sizes, int n_in,
                              void* d_out, int out_size)
{
    const float* x     = (const float*)d_in[0];
    const int*   tgt   = (const int*)  d_in[1];
    const int*   neigh = (const int*)  d_in[2];
    const float* fc_w  = (const float*)d_in[3];
    const float* fc_b  = (const float*)d_in[4];
    const float* q_w   = (const float*)d_in[5];
    const float* q_b   = (const float*)d_in[6];
    const float* k_w   = (const float*)d_in[7];
    const float* k_b   = (const float*)d_in[8];
    const float* v_w   = (const float*)d_in[9];
    const float* v_b   = (const float*)d_in[10];
    const float* att_W = (const float*)d_in[11];
    const float* a1w   = (const float*)d_in[12];
    const float* a1b   = (const float*)d_in[13];
    const float* a2w   = (const float*)d_in[14];
    const float* a2b   = (const float*)d_in[15];
    const float* ip1w  = (const float*)d_in[16];
    const float* ip1b  = (const float*)d_in[17];
    const float* ip2w  = (const float*)d_in[18];
    const float* bp1w  = (const float*)d_in[19];
    const float* bp1b  = (const float*)d_in[20];
    const float* bp2w  = (const float*)d_in[21];
    float* out = (float*)d_out;

    float *ckw, *ckb, *cqw, *cqb, *xsh, *ysh, *h1, *vh, *h2, *wh2, *sout, *mp;
    cudaGetSymbolAddress((void**)&ckw,  g_ckw);
    cudaGetSymbolAddress((void**)&ckb,  g_ckb);
    cudaGetSymbolAddress((void**)&cqw,  g_cqw);
    cudaGetSymbolAddress((void**)&cqb,  g_cqb);
    cudaGetSymbolAddress((void**)&xsh,  g_xsh);
    cudaGetSymbolAddress((void**)&ysh,  g_ysh);
    cudaGetSymbolAddress((void**)&h1,   g_h1);
    cudaGetSymbolAddress((void**)&vh,   g_vh);
    cudaGetSymbolAddress((void**)&h2,   g_h2);
    cudaGetSymbolAddress((void**)&wh2,  g_wh2);
    cudaGetSymbolAddress((void**)&sout, g_sout);
    cudaGetSymbolAddress((void**)&mp,   g_mp);

    // 1. fold attention-layer weights into k/q projections
    combine_w<<<dim3(H, PAIRS), H>>>(a1w, a1b, k_w, k_b, ckw, ckb);
    combine_w<<<dim3(H, PAIRS), H>>>(a2w, a2b, q_w, q_b, cqw, cqb);

    // 2. shared fc + leakyrelu on gathered neighbors + targets
    fc_gemm<<<dim3(R_/128, 4, S), 256>>>(x, neigh, tgt, fc_w, fc_b, ysh, xsh);

    // 3. h1 = lrelu(ysh @ ck^T + ckb);  vh = ysh @ v_w^T + v_b
    gemm128<<<dim3(BM_/128, PAIRS), 256>>>(ysh, ckw, ckb, h1, BM_, 1, 0);
    gemm128<<<dim3(BM_/128, PAIRS), 256>>>(ysh, v_w, v_b, vh, BM_, 0, 0);

    // 4. h2 = lrelu(xsh @ cq^T + cqb);  wh2 = h2 @ att_W^T
    gemm128<<<dim3(Bq/128, PAIRS), 256>>>(xsh, cqw, cqb, h2, Bq, 1, 0);
    gemm128<<<dim3(Bq/128, PAIRS), 256>>>(h2, att_W, nullptr, wh2, Bq, 0, 1);

    // 5. attention scores + softmax + V aggregation + residual
    attn_combine<<<dim3(Bq, PAIRS), 128>>>(h1, vh, wh2, xsh, sout);

    // 6. semantic attention within each metapath
    semantic<2><<<Bq/4, 128>>>(sout,            ip1w,       ip1b,     ip2w,     mp,       Bq*D, D, KM*D);
    semantic<3><<<Bq/4, 128>>>(sout + 2*Bq*D,   ip1w + H*D, ip1b + H, ip2w + H, mp + D,   Bq*D, D, KM*D);

    // 7. semantic attention between metapaths -> final output
    semantic<2><<<Bq/4, 128>>>(mp, bp1w, bp1b, bp2w, out, D, KM*D, D);
}

// round 3
// speedup vs baseline: 1.5253x; 1.5253x over previous
#include <cuda_runtime.h>
#include <cuda_bf16.h>
#include <math.h>

#define NN    20000
#define IN_F  256
#define H     128
#define HN    4
#define S     5
#define KM    2
#define Bq    1024
#define M     16
#define D     512
#define ALPHA 0.2f
#define BM_   (Bq*M)      /* 16384 */
#define R_    (BM_ + Bq)  /* 17408 */
#define PAIRS (S*HN)      /* 20 */

#define KC    32          /* K-chunk per pipeline stage */
#define ASTR  36          /* KC + 4 pad (floats) */

__constant__ int c_kofs[S] = {0,0,1,1,1};

// ---------------- scratch ----------------
__device__ float g_ckw[PAIRS*H*H];
__device__ float g_ckb[PAIRS*H];
__device__ float g_cqw[PAIRS*H*H];
__device__ float g_cqb[PAIRS*H];
__device__ float g_xsh[PAIRS*Bq*H];
__device__ float g_ysh[PAIRS*BM_*H];
__device__ float g_h2 [PAIRS*Bq*H];
__device__ float g_wh2[PAIRS*Bq*H];
__device__ float g_sout[S*Bq*D];
__device__ float g_mp[Bq*KM*D];

// ---------------- helpers ----------------
__device__ __forceinline__ void mma_tf32(float* d, const unsigned* a, const unsigned* b) {
    asm volatile(
      "mma.sync.aligned.m16n8k8.row.col.f32.tf32.tf32.f32 "
      "{%0,%1,%2,%3}, {%4,%5,%6,%7}, {%8,%9}, {%0,%1,%2,%3};\n"
      : "+f"(d[0]), "+f"(d[1]), "+f"(d[2]), "+f"(d[3])
      : "r"(a[0]), "r"(a[1]), "r"(a[2]), "r"(a[3]), "r"(b[0]), "r"(b[1]));
}
__device__ __forceinline__ unsigned f2tf32(float x) {
    unsigned r;
    asm("cvt.rna.tf32.f32 %0, %1;\n" : "=r"(r) : "f"(x));
    return r;
}
__device__ __forceinline__ void split_tf32(float x, unsigned& hi, unsigned& lo) {
    hi = f2tf32(x);
    lo = f2tf32(x - __uint_as_float(hi));
}
__device__ __forceinline__ void cpa16(void* dst, const void* src) {
    unsigned d = (unsigned)__cvta_generic_to_shared(dst);
    asm volatile("cp.async.cg.shared.global [%0], [%1], 16;\n" :: "r"(d), "l"(src));
}
__device__ __forceinline__ void cp_commit() { asm volatile("cp.async.commit_group;\n"); }
__device__ __forceinline__ void cp_wait1() { asm volatile("cp.async.wait_group 1;\n"); }
__device__ __forceinline__ void cp_wait0() { asm volatile("cp.async.wait_group 0;\n"); }
__device__ __forceinline__ float lrelu_f(float v) { return v >= 0.f ? v : ALPHA*v; }

// ---------------- combined weights: cw = a @ w, cb = a @ wb + ab ----------------
__global__ void combine_w(const float* __restrict__ aw, const float* __restrict__ ab,
                          const float* __restrict__ w,  const float* __restrict__ wb,
                          float* __restrict__ cw, float* __restrict__ cb)
{
    int o = blockIdx.x, z = blockIdx.y, tid = threadIdx.x;
    int s = z / HN, h = z % HN;
    int kz = c_kofs[s]*HN + h;
    const float* arow = aw + ((size_t)kz*H + o)*H;
    const float* wm   = w  + (size_t)z*H*H;
    __shared__ float sa[H];
    sa[tid] = arow[tid];
    __syncthreads();
    float acc = 0.f;
    #pragma unroll 8
    for (int j = 0; j < H; ++j) acc += sa[j]*wm[j*H + tid];
    cw[((size_t)z*H + o)*H + tid] = acc;
    if (tid == 0) {
        float bacc = ab[kz*H + o];
        const float* kb = wb + z*H;
        for (int j = 0; j < H; ++j) bacc += sa[j]*kb[j];
        cb[z*H + o] = bacc;
    }
}

// ================= fc GEMM (3xTF32 tensor core, gather) =================
// C[128x128] = lrelu(x[rows] @ fcw[s,nt-head]^T + b), K=256.
#define FC_SMEM (4*128*ASTR*4 + 512)
__global__ __launch_bounds__(256,2) void fc_tf32(
    const float* __restrict__ x, const int* __restrict__ neigh,
    const int* __restrict__ tgt, const float* __restrict__ fcw,
    const float* __restrict__ fcb, float* __restrict__ ysh, float* __restrict__ xsh)
{
    extern __shared__ float sm[];
    float* As = sm;                       // 2*128*ASTR
    float* Bs = sm + 2*128*ASTR;
    int*   rows = (int*)(sm + 4*128*ASTR);
    int mt = blockIdx.x, nt = blockIdx.y, s = blockIdx.z;
    int tid = threadIdx.x;
    if (tid < 128) {
        int r = mt*128 + tid;
        rows[tid] = (r < BM_) ? neigh[s*BM_ + r] : tgt[r - BM_];
    }
    __syncthreads();
    const float* wbase = fcw + ((size_t)s*512 + nt*128)*IN_F;

    int lr = tid >> 3, lk = (tid & 7)*4;
    auto prefetch = [&](int kc, int buf) {
        float* A = As + buf*128*ASTR;
        float* B = Bs + buf*128*ASTR;
        #pragma unroll
        for (int t = 0; t < 4; ++t) {
            int r = lr + t*32;
            cpa16(A + r*ASTR + lk, x + (size_t)rows[r]*IN_F + kc*KC + lk);
            cpa16(B + r*ASTR + lk, wbase + (size_t)r*IN_F + kc*KC + lk);
        }
    };

    int w = tid >> 5, lane = tid & 31, gid = lane >> 2, tig = lane & 3;
    int wm = (w & 3)*32, wn = (w >> 2)*64;
    float acc[2][8][4];
    #pragma unroll
    for (int i = 0; i < 2; ++i)
        #pragma unroll
        for (int j = 0; j < 8; ++j)
            #pragma unroll
            for (int e = 0; e < 4; ++e) acc[i][j][e] = 0.f;

    prefetch(0, 0); cp_commit();
    const int NCH = IN_F/KC;  // 8
    for (int kc = 0; kc < NCH; ++kc) {
        if (kc+1 < NCH) { prefetch(kc+1, (kc+1)&1); cp_commit(); cp_wait1(); }
        else            { cp_wait0(); }
        __syncthreads();
        const float* A = As + (kc&1)*128*ASTR;
        const float* B = Bs + (kc&1)*128*ASTR;
        #pragma unroll
        for (int ks = 0; ks < KC; ks += 8) {
            unsigned ah[2][4], al[2][4];
            #pragma unroll
            for (int mi = 0; mi < 2; ++mi) {
                int m0 = wm + mi*16 + gid;
                split_tf32(A[m0*ASTR + ks + tig],       ah[mi][0], al[mi][0]);
                split_tf32(A[(m0+8)*ASTR + ks + tig],   ah[mi][1], al[mi][1]);
                split_tf32(A[m0*ASTR + ks + 4 + tig],   ah[mi][2], al[mi][2]);
                split_tf32(A[(m0+8)*ASTR + ks + 4 + tig], ah[mi][3], al[mi][3]);
            }
            #pragma unroll
            for (int ni = 0; ni < 8; ++ni) {
                int n0 = wn + ni*8 + gid;
                unsigned bh[2], bl[2];
                split_tf32(B[n0*ASTR + ks + tig],     bh[0], bl[0]);
                split_tf32(B[n0*ASTR + ks + 4 + tig], bh[1], bl[1]);
                #pragma unroll
                for (int mi = 0; mi < 2; ++mi) {
                    mma_tf32(acc[mi][ni], al[mi], bh);
                    mma_tf32(acc[mi][ni], ah[mi], bl);
                    mma_tf32(acc[mi][ni], ah[mi], bh);
                }
            }
        }
        __syncthreads();
    }

    // epilogue: bias+lrelu -> smem (reuse As) -> coalesced f4 stores
    int zp = s*HN + nt;
    float* Cs = As;  // 128x132
    #pragma unroll
    for (int mi = 0; mi < 2; ++mi)
        #pragma unroll
        for (int ni = 0; ni < 8; ++ni)
            #pragma unroll
            for (int e = 0; e < 4; ++e) {
                int r = wm + mi*16 + gid + ((e >= 2) ? 8 : 0);
                int c = wn + ni*8 + 2*tig + (e & 1);
                Cs[r*132 + c] = lrelu_f(acc[mi][ni][e] + fcb[zp*H + c]);
            }
    __syncthreads();
    #pragma unroll
    for (int t = 0; t < 16; ++t) {
        int idx = tid + t*256;                 // f4 index, 4096 total
        int rr = idx >> 5, c4 = (idx & 31)*4;
        float4 v = *(const float4*)(Cs + rr*132 + c4);
        int gr = mt*128 + rr;
        float* dst = (gr < BM_) ? (ysh + ((size_t)zp*BM_ + gr)*H + c4)
                                : (xsh + ((size_t)zp*Bq + (gr - BM_))*H + c4);
        *(float4*)dst = v;
    }
}

// ================= fused h1/vh GEMM + attention (3xTF32) =================
// Per block: pair z, 128 rows (8 targets). One 128x256 GEMM (B = [ckw | v_w]),
// then bilinear score, softmax over M=16, lrelu-weighted V sum, residual.
#define FU_GEMM_FLOATS (2*128*ASTR + 2*256*ASTR)
#define FU_EPI_FLOATS  (128*132 + 128*132 + 8*128 + 128 + 128)
#define FU_SMEM        (FU_EPI_FLOATS > FU_GEMM_FLOATS ? FU_EPI_FLOATS*4 : FU_GEMM_FLOATS*4)
__global__ __launch_bounds__(512,1) void fused_attn(
    const float* __restrict__ ysh, const float* __restrict__ ckw,
    const float* __restrict__ ckb, const float* __restrict__ vw,
    const float* __restrict__ vb,  const float* __restrict__ wh2,
    const float* __restrict__ xsh, float* __restrict__ sout)
{
    extern __shared__ float sm[];
    float* As = sm;                 // 2*128*ASTR
    float* Bs = sm + 2*128*ASTR;    // 2*256*ASTR
    int mt = blockIdx.x, z = blockIdx.y;
    int tid = threadIdx.x;

    const float* Ag = ysh + ((size_t)z*BM_ + mt*128)*H;
    const float* Wk = ckw + (size_t)z*H*H;
    const float* Wv = vw  + (size_t)z*H*H;

    int lr = tid >> 3, lk = (tid & 7)*4;
    auto prefetch = [&](int kc, int buf) {
        float* A = As + buf*128*ASTR;
        float* B = Bs + buf*256*ASTR;
        #pragma unroll
        for (int t = 0; t < 2; ++t) {       // A: 1024 f4 / 512 thr
            int r = lr + t*64;
            cpa16(A + r*ASTR + lk, Ag + (size_t)r*H + kc*KC + lk);
        }
        #pragma unroll
        for (int t = 0; t < 4; ++t) {       // B: 2048 f4 / 512 thr
            int n = lr + t*64;
            const float* src = (n < 128) ? (Wk + (size_t)n*H + kc*KC + lk)
                                         : (Wv + (size_t)(n-128)*H + kc*KC + lk);
            cpa16(B + n*ASTR + lk, src);
        }
    };

    int w = tid >> 5, lane = tid & 31, gid = lane >> 2, tig = lane & 3;
    int wm = (w & 3)*32, wn = (w >> 2)*64;
    float acc[2][8][4];
    #pragma unroll
    for (int i = 0; i < 2; ++i)
        #pragma unroll
        for (int j = 0; j < 8; ++j)
            #pragma unroll
            for (int e = 0; e < 4; ++e) acc[i][j][e] = 0.f;

    prefetch(0, 0); cp_commit();
    const int NCH = H/KC;  // 4
    for (int kc = 0; kc < NCH; ++kc) {
        if (kc+1 < NCH) { prefetch(kc+1, (kc+1)&1); cp_commit(); cp_wait1(); }
        else            { cp_wait0(); }
        __syncthreads();
        const float* A = As + (kc&1)*128*ASTR;
        const float* B = Bs + (kc&1)*256*ASTR;
        #pragma unroll
        for (int ks = 0; ks < KC; ks += 8) {
            unsigned ah[2][4], al[2][4];
            #pragma unroll
            for (int mi = 0; mi < 2; ++mi) {
                int m0 = wm + mi*16 + gid;
                split_tf32(A[m0*ASTR + ks + tig],         ah[mi][0], al[mi][0]);
                split_tf32(A[(m0+8)*ASTR + ks + tig],     ah[mi][1], al[mi][1]);
                split_tf32(A[m0*ASTR + ks + 4 + tig],     ah[mi][2], al[mi][2]);
                split_tf32(A[(m0+8)*ASTR + ks + 4 + tig], ah[mi][3], al[mi][3]);
            }
            #pragma unroll
            for (int ni = 0; ni < 8; ++ni) {
                int n0 = wn + ni*8 + gid;
                unsigned bh[2], bl[2];
                split_tf32(B[n0*ASTR + ks + tig],     bh[0], bl[0]);
                split_tf32(B[n0*ASTR + ks + 4 + tig], bh[1], bl[1]);
                #pragma unroll
                for (int mi = 0; mi < 2; ++mi) {
                    mma_tf32(acc[mi][ni], al[mi], bh);
                    mma_tf32(acc[mi][ni], ah[mi], bl);
                    mma_tf32(acc[mi][ni], ah[mi], bh);
                }
            }
        }
        __syncthreads();
    }

    // epilogue smem (aliases GEMM buffers; all compute done)
    float* SP  = sm;                 // [128][132]  h1 (lrelu+bias)
    float* SV  = SP + 128*132;       // [128][132]  vh (+bias)
    float* SW  = SV + 128*132;       // [8][128]    wh2 rows
    float* SSC = SW + 8*128;         // [128] scores
    float* SE  = SSC + 128;          // [128] softmax weights

    #pragma unroll
    for (int mi = 0; mi < 2; ++mi)
        #pragma unroll
        for (int ni = 0; ni < 8; ++ni)
            #pragma unroll
            for (int e = 0; e < 4; ++e) {
                int r = wm + mi*16 + gid + ((e >= 2) ? 8 : 0);
                int c = wn + ni*8 + 2*tig + (e & 1);
                float v = acc[mi][ni][e];
                if (c < 128) SP[r*132 + c] = lrelu_f(v + ckb[z*H + c]);
                else         SV[r*132 + (c-128)] = v + vb[z*H + (c-128)];
            }
    #pragma unroll
    for (int t = 0; t < 2; ++t) {
        int idx = tid + t*512;       // 1024 = 8 b x 128
        int bl = idx >> 7, o = idx & 127;
        SW[idx] = wh2[((size_t)z*Bq + mt*8 + bl)*H + o];
    }
    __syncthreads();

    // scores: warp w -> rows w*8 .. w*8+7
    #pragma unroll
    for (int i = 0; i < 8; ++i) {
        int rr = w*8 + i;
        const float* wrow = SW + (rr >> 4)*128;
        float p = 0.f;
        #pragma unroll
        for (int o = 0; o < 128; o += 32) p += SP[rr*132 + o + lane]*wrow[o + lane];
        #pragma unroll
        for (int d_ = 16; d_ > 0; d_ >>= 1) p += __shfl_xor_sync(0xffffffffu, p, d_);
        if (lane == 0) SSC[rr] = p;
    }
    __syncthreads();
    if (tid < 8) {
        float mx = -1e30f;
        #pragma unroll
        for (int m = 0; m < M; ++m) mx = fmaxf(mx, SSC[tid*M + m]);
        float es[M], sum = 0.f;
        #pragma unroll
        for (int m = 0; m < M; ++m) { es[m] = expf(SSC[tid*M + m] - mx); sum += es[m]; }
        float inv = 1.f/sum;
        #pragma unroll
        for (int m = 0; m < M; ++m) SE[tid*M + m] = es[m]*inv;
    }
    __syncthreads();

    int s = z/HN, hh = z%HN;
    #pragma unroll
    for (int t = 0; t < 2; ++t) {
        int idx = tid + t*512;
        int bl = idx >> 7, o = idx & 127;
        float a = 0.f;
        #pragma unroll
        for (int m = 0; m < M; ++m) {
            float v = SV[(bl*M + m)*132 + o]*SE[bl*M + m];
            a += (v >= 0.f) ? v : ALPHA*v;
        }
        int b = mt*8 + bl;
        sout[((size_t)s*Bq + b)*D + hh*H + o] =
            0.5f*(xsh[((size_t)z*Bq + b)*H + o] + a);
    }
}

// ---------------- small fp32 GEMM for h2 / wh2 ----------------
__global__ __launch_bounds__(256) void gemm128(
    const float* __restrict__ Abase, const float* __restrict__ Wbase,
    const float* __restrict__ biasBase, float* __restrict__ Cbase,
    int Mrows, int doLrelu, int wKmap)
{
    int mt = blockIdx.x, z = blockIdx.y;
    int wz = z;
    if (wKmap) wz = c_kofs[z/HN]*HN + (z % HN);
    const float* A = Abase + (size_t)z*Mrows*H;
    const float* W = Wbase + (size_t)wz*H*H;
    float*       C = Cbase + (size_t)z*Mrows*H;
    int tid = threadIdx.x;
    __shared__ float As[8][132];
    __shared__ float Bs[8][132];
    int tx = tid & 15, ty = tid >> 4;
    int la_r = tid >> 1, la_k = (tid & 1)*4;
    float acc[8][8];
    #pragma unroll
    for (int i = 0; i < 8; ++i)
        #pragma unroll
        for (int j = 0; j < 8; ++j) acc[i][j] = 0.f;
    const float* arow = A + ((size_t)mt*128 + la_r)*H + la_k;
    const float* brow = W + (size_t)la_r*H + la_k;
    for (int k0 = 0; k0 < H; k0 += 8) {
        float4 av = *(const float4*)(arow + k0);
        float4 bv = *(const float4*)(brow + k0);
        As[la_k+0][la_r]=av.x; As[la_k+1][la_r]=av.y; As[la_k+2][la_r]=av.z; As[la_k+3][la_r]=av.w;
        Bs[la_k+0][la_r]=bv.x; Bs[la_k+1][la_r]=bv.y; Bs[la_k+2][la_r]=bv.z; Bs[la_k+3][la_r]=bv.w;
        __syncthreads();
        #pragma unroll
        for (int kk = 0; kk < 8; ++kk) {
            float4 a0 = *(const float4*)&As[kk][ty*8];
            float4 a1 = *(const float4*)&As[kk][ty*8+4];
            float4 b0 = *(const float4*)&Bs[kk][tx*8];
            float4 b1 = *(const float4*)&Bs[kk][tx*8+4];
            float ra[8] = {a0.x,a0.y,a0.z,a0.w,a1.x,a1.y,a1.z,a1.w};
            float rb[8] = {b0.x,b0.y,b0.z,b0.w,b1.x,b1.y,b1.z,b1.w};
            #pragma unroll
            for (int i = 0; i < 8; ++i)
                #pragma unroll
                for (int j = 0; j < 8; ++j) acc[i][j] += ra[i]*rb[j];
        }
        __syncthreads();
    }
    float bj[8];
    #pragma unroll
    for (int j = 0; j < 8; ++j) bj[j] = biasBase ? biasBase[z*H + tx*8 + j] : 0.f;
    #pragma unroll
    for (int i = 0; i < 8; ++i) {
        int r = mt*128 + ty*8 + i;
        #pragma unroll
        for (int j = 0; j < 8; ++j) {
            int o = tx*8 + j;
            float v = acc[i][j] + bj[j];
            if (doLrelu) v = v >= 0.f ? v : ALPHA*v;
            C[(size_t)r*H + o] = v;
        }
    }
}

// ---------------- semantic attention ----------------
template<int P>
__global__ __launch_bounds__(128) void semantic(
    const float* __restrict__ zin, const float* __restrict__ p1w,
    const float* __restrict__ p1b, const float* __restrict__ p2w,
    float* __restrict__ outp, int in_pstride, int in_bstride, int out_bstride)
{
    int b0 = blockIdx.x*4, tid = threadIdx.x;
    __shared__ float zs[4][P][D];
    int tot = 4*P*D;
    for (int idx = tid; idx < tot; idx += 128) {
        int d = idx % D; int rp = idx / D; int p = rp % P; int bl = rp / P;
        zs[bl][p][d] = zin[(size_t)(b0+bl)*in_bstride + (size_t)p*in_pstride + d];
    }
    __syncthreads();
    float acc[4][P];
    #pragma unroll
    for (int bl = 0; bl < 4; ++bl)
        #pragma unroll
        for (int p = 0; p < P; ++p) acc[bl][p] = 0.f;
    const float* wrow = p1w + (size_t)tid*D;
    for (int d = 0; d < D; ++d) {
        float wv = wrow[d];
        #pragma unroll
        for (int bl = 0; bl < 4; ++bl)
            #pragma unroll
            for (int p = 0; p < P; ++p) acc[bl][p] += wv*zs[bl][p][d];
    }
    float bias = p1b[tid], p2 = p2w[tid];
    __shared__ float sred[4*P][132];
    __shared__ float ssc[4*P];
    #pragma unroll
    for (int bl = 0; bl < 4; ++bl)
        #pragma unroll
        for (int p = 0; p < P; ++p)
            sred[bl*P+p][tid] = tanhf(acc[bl][p] + bias)*p2;
    __syncthreads();
    if (tid < 4*P) {
        float s_ = 0.f;
        for (int o = 0; o < H; ++o) s_ += sred[tid][o];
        ssc[tid] = s_;
    }
    __syncthreads();
    #pragma unroll
    for (int bl = 0; bl < 4; ++bl) {
        float mx = -1e30f;
        #pragma unroll
        for (int p = 0; p < P; ++p) mx = fmaxf(mx, ssc[bl*P+p]);
        float e[P]; float esum = 0.f;
        #pragma unroll
        for (int p = 0; p < P; ++p) { e[p] = expf(ssc[bl*P+p] - mx); esum += e[p]; }
        float inv = 1.f/esum;
        for (int d = tid; d < D; d += 128) {
            float o_ = 0.f;
            #pragma unroll
            for (int p = 0; p < P; ++p) o_ += e[p]*zs[bl][p][d];
            outp[(size_t)(b0+bl)*out_bstride + d] = o_*inv;
        }
    }
}

extern "C" void kernel_launch(void* const* d_in, const int* in_sizes, int n_in,
                              void* d_out, int out_size)
{
    const float* x     = (const float*)d_in[0];
    const int*   tgt   = (const int*)  d_in[1];
    const int*   neigh = (const int*)  d_in[2];
    const float* fc_w  = (const float*)d_in[3];
    const float* fc_b  = (const float*)d_in[4];
    const float* q_w   = (const float*)d_in[5];
    const float* q_b   = (const float*)d_in[6];
    const float* k_w   = (const float*)d_in[7];
    const float* k_b   = (const float*)d_in[8];
    const float* v_w   = (const float*)d_in[9];
    const float* v_b   = (const float*)d_in[10];
    const float* att_W = (const float*)d_in[11];
    const float* a1w   = (const float*)d_in[12];
    const float* a1b   = (const float*)d_in[13];
    const float* a2w   = (const float*)d_in[14];
    const float* a2b   = (const float*)d_in[15];
    const float* ip1w  = (const float*)d_in[16];
    const float* ip1b  = (const float*)d_in[17];
    const float* ip2w  = (const float*)d_in[18];
    const float* bp1w  = (const float*)d_in[19];
    const float* bp1b  = (const float*)d_in[20];
    const float* bp2w  = (const float*)d_in[21];
    float* out = (float*)d_out;

    float *ckw, *ckb, *cqw, *cqb, *xsh, *ysh, *h2, *wh2, *sout, *mp;
    cudaGetSymbolAddress((void**)&ckw,  g_ckw);
    cudaGetSymbolAddress((void**)&ckb,  g_ckb);
    cudaGetSymbolAddress((void**)&cqw,  g_cqw);
    cudaGetSymbolAddress((void**)&cqb,  g_cqb);
    cudaGetSymbolAddress((void**)&xsh,  g_xsh);
    cudaGetSymbolAddress((void**)&ysh,  g_ysh);
    cudaGetSymbolAddress((void**)&h2,   g_h2);
    cudaGetSymbolAddress((void**)&wh2,  g_wh2);
    cudaGetSymbolAddress((void**)&sout, g_sout);
    cudaGetSymbolAddress((void**)&mp,   g_mp);

    static int smem_set = 0;
    if (!smem_set) {
        cudaFuncSetAttribute(fc_tf32,    cudaFuncAttributeMaxDynamicSharedMemorySize, FC_SMEM);
        cudaFuncSetAttribute(fused_attn, cudaFuncAttributeMaxDynamicSharedMemorySize, FU_SMEM);
        smem_set = 1;
    }

    // 1. fold attention-layer weights into k/q projections
    combine_w<<<dim3(H, PAIRS), H>>>(a1w, a1b, k_w, k_b, ckw, ckb);
    combine_w<<<dim3(H, PAIRS), H>>>(a2w, a2b, q_w, q_b, cqw, cqb);

    // 2. shared fc + leakyrelu on gathered neighbors + targets (3xTF32 TC)
    fc_tf32<<<dim3(R_/128, 4, S), 256, FC_SMEM>>>(x, neigh, tgt, fc_w, fc_b, ysh, xsh);

    // 3. h2 = lrelu(xsh @ cq^T + cqb);  wh2 = h2 @ att_W^T  (small)
    gemm128<<<dim3(Bq/128, PAIRS), 256>>>(xsh, cqw, cqb, h2, Bq, 1, 0);
    gemm128<<<dim3(Bq/128, PAIRS), 256>>>(h2, att_W, nullptr, wh2, Bq, 0, 1);

    // 4. fused h1/vh GEMM + neighbor attention + residual (3xTF32)
    fused_attn<<<dim3(BM_/128, PAIRS), 512, FU_SMEM>>>(ysh, ckw, ckb, v_w, v_b, wh2, xsh, sout);

    // 5. semantic attention within each metapath
    semantic<2><<<Bq/4, 128>>>(sout,          ip1w,       ip1b,     ip2w,     mp,     Bq*D, D, KM*D);
    semantic<3><<<Bq/4, 128>>>(sout + 2*Bq*D, ip1w + H*D, ip1b + H, ip2w + H, mp + D, Bq*D, D, KM*D);

    // 6. semantic attention between metapaths -> final output
    semantic<2><<<Bq/4, 128>>>(mp, bp1w, bp1b, bp2w, out, D, KM*D, D);
}

// round 4
// speedup vs baseline: 2.0167x; 1.3222x over previous
#include <cuda_runtime.h>
#include <cuda_bf16.h>
#include <math.h>

#define NN    20000
#define IN_F  256
#define H     128
#define HN    4
#define S     5
#define KM    2
#define Bq    1024
#define M     16
#define D     512
#define ALPHA 0.2f
#define BM_   (Bq*M)      /* 16384 */
#define R_    (BM_ + Bq)  /* 17408 */
#define PAIRS (S*HN)      /* 20 */

#define KC    32          /* K halves per pipeline stage */
#define HS    40          /* smem row stride in halves (KC + 8 pad) */

__constant__ int c_kofs[S] = {0,0,1,1,1};

// ---------------- scratch ----------------
__device__ __nv_bfloat16 g_xhi[NN*IN_F];
__device__ __nv_bfloat16 g_xlo[NN*IN_F];
__device__ __nv_bfloat16 g_fwh[S*4*H*IN_F];
__device__ __nv_bfloat16 g_fwl[S*4*H*IN_F];
__device__ __nv_bfloat16 g_vwh[PAIRS*H*H];
__device__ __nv_bfloat16 g_vwl[PAIRS*H*H];
__device__ __nv_bfloat16 g_ckwh[PAIRS*H*H];
__device__ __nv_bfloat16 g_ckwl[PAIRS*H*H];
__device__ float g_ckb[PAIRS*H];
__device__ float g_cqw[PAIRS*H*H];
__device__ float g_cqb[PAIRS*H];
__device__ float g_xsh[PAIRS*Bq*H];
__device__ __nv_bfloat16 g_yh[(size_t)PAIRS*BM_*H];
__device__ __nv_bfloat16 g_yl[(size_t)PAIRS*BM_*H];
__device__ float g_h2 [PAIRS*Bq*H];
__device__ float g_wh2[PAIRS*Bq*H];
__device__ float g_sout[S*Bq*D];
__device__ float g_mp[Bq*KM*D];

// ---------------- helpers ----------------
__device__ __forceinline__ void mma_bf16(float* d, const unsigned* a, const unsigned* b) {
    asm volatile(
      "mma.sync.aligned.m16n8k16.row.col.f32.bf16.bf16.f32 "
      "{%0,%1,%2,%3}, {%4,%5,%6,%7}, {%8,%9}, {%0,%1,%2,%3};\n"
      : "+f"(d[0]), "+f"(d[1]), "+f"(d[2]), "+f"(d[3])
      : "r"(a[0]), "r"(a[1]), "r"(a[2]), "r"(a[3]), "r"(b[0]), "r"(b[1]));
}
__device__ __forceinline__ void split_bf(float x, __nv_bfloat16& h, __nv_bfloat16& l) {
    h = __float2bfloat16_rn(x);
    l = __float2bfloat16_rn(x - __bfloat162float(h));
}
__device__ __forceinline__ void cpa16(void* dst, const void* src) {
    unsigned d = (unsigned)__cvta_generic_to_shared(dst);
    asm volatile("cp.async.cg.shared.global [%0], [%1], 16;\n" :: "r"(d), "l"(src));
}
__device__ __forceinline__ void cp_commit() { asm volatile("cp.async.commit_group;\n"); }
__device__ __forceinline__ void cp_wait1() { asm volatile("cp.async.wait_group 1;\n"); }
__device__ __forceinline__ void cp_wait0() { asm volatile("cp.async.wait_group 0;\n"); }
__device__ __forceinline__ float lrelu_f(float v) { return v >= 0.f ? v : ALPHA*v; }

// ---------------- generic fp32 -> bf16 hi/lo split ----------------
__global__ void split2(const float* __restrict__ in, __nv_bfloat16* __restrict__ hi,
                       __nv_bfloat16* __restrict__ lo, int n)
{
    int i = blockIdx.x*256 + threadIdx.x;
    if (i < n) split_bf(in[i], hi[i], lo[i]);
}

// ---------------- combined weights (fp32 out, for cq) ----------------
__global__ void combine_w(const float* __restrict__ aw, const float* __restrict__ ab,
                          const float* __restrict__ w,  const float* __restrict__ wb,
                          float* __restrict__ cw, float* __restrict__ cb)
{
    int o = blockIdx.x, z = blockIdx.y, tid = threadIdx.x;
    int s = z / HN, h = z % HN;
    int kz = c_kofs[s]*HN + h;
    const float* arow = aw + ((size_t)kz*H + o)*H;
    const float* wm   = w  + (size_t)z*H*H;
    __shared__ float sa[H];
    sa[tid] = arow[tid];
    __syncthreads();
    float acc = 0.f;
    #pragma unroll 8
    for (int j = 0; j < H; ++j) acc += sa[j]*wm[j*H + tid];
    cw[((size_t)z*H + o)*H + tid] = acc;
    if (tid == 0) {
        float bacc = ab[kz*H + o];
        const float* kb = wb + z*H;
        for (int j = 0; j < H; ++j) bacc += sa[j]*kb[j];
        cb[z*H + o] = bacc;
    }
}

// ---------------- combined weights (bf16 hi/lo out, for ck) ----------------
__global__ void combine_w_b(const float* __restrict__ aw, const float* __restrict__ ab,
                            const float* __restrict__ w,  const float* __restrict__ wb,
                            __nv_bfloat16* __restrict__ cwh, __nv_bfloat16* __restrict__ cwl,
                            float* __restrict__ cb)
{
    int o = blockIdx.x, z = blockIdx.y, tid = threadIdx.x;
    int s = z / HN, h = z % HN;
    int kz = c_kofs[s]*HN + h;
    const float* arow = aw + ((size_t)kz*H + o)*H;
    const float* wm   = w  + (size_t)z*H*H;
    __shared__ float sa[H];
    sa[tid] = arow[tid];
    __syncthreads();
    float acc = 0.f;
    #pragma unroll 8
    for (int j = 0; j < H; ++j) acc += sa[j]*wm[j*H + tid];
    size_t idx = ((size_t)z*H + o)*H + tid;
    split_bf(acc, cwh[idx], cwl[idx]);
    if (tid == 0) {
        float bacc = ab[kz*H + o];
        const float* kb = wb + z*H;
        for (int j = 0; j < H; ++j) bacc += sa[j]*kb[j];
        cb[z*H + o] = bacc;
    }
}

// ================= fc GEMM (bf16-split tensor core, gather) =================
// C[128x128] = lrelu(x[rows] @ fcw^T + b), K=256. grid (136,4,5), block 256.
#define FC2_SMEM (8*128*HS*2 + 512)
__global__ __launch_bounds__(256,2) void fc_bf16(
    const __nv_bfloat16* __restrict__ xh, const __nv_bfloat16* __restrict__ xl,
    const int* __restrict__ neigh, const int* __restrict__ tgt,
    const __nv_bfloat16* __restrict__ fwh, const __nv_bfloat16* __restrict__ fwl,
    const float* __restrict__ fcb,
    __nv_bfloat16* __restrict__ yh, __nv_bfloat16* __restrict__ yl,
    float* __restrict__ xsh)
{
    extern __shared__ __align__(16) char smc[];
    __nv_bfloat16* Ah = (__nv_bfloat16*)smc;       // [2][128*HS]
    __nv_bfloat16* Al = Ah + 2*128*HS;
    __nv_bfloat16* Bh = Al + 2*128*HS;
    __nv_bfloat16* Bl = Bh + 2*128*HS;
    int* rows = (int*)(Bl + 2*128*HS);
    int mt = blockIdx.x, nt = blockIdx.y, s = blockIdx.z;
    int tid = threadIdx.x;
    if (tid < 128) {
        int r = mt*128 + tid;
        rows[tid] = (r < BM_) ? neigh[s*BM_ + r] : tgt[r - BM_];
    }
    __syncthreads();
    size_t wb = ((size_t)s*512 + nt*128)*IN_F;

    auto prefetch = [&](int kc, int buf) {
        #pragma unroll
        for (int i = 0; i < 2; ++i) {
            int idx = tid + i*256;             // 512 transfers of 8 halves
            int r = idx >> 2, seg = (idx & 3)*8;
            int so = buf*128*HS + r*HS + seg;
            size_t ga = (size_t)rows[r]*IN_F + kc*KC + seg;
            size_t gb = wb + (size_t)r*IN_F + kc*KC + seg;
            cpa16(Ah + so, xh + ga);
            cpa16(Al + so, xl + ga);
            cpa16(Bh + so, fwh + gb);
            cpa16(Bl + so, fwl + gb);
        }
    };

    int w = tid >> 5, lane = tid & 31, gid = lane >> 2, tig = lane & 3;
    int wm = (w & 3)*32, wn = (w >> 2)*64;
    float acc[2][8][4];
    #pragma unroll
    for (int i = 0; i < 2; ++i)
        #pragma unroll
        for (int j = 0; j < 8; ++j)
            #pragma unroll
            for (int e = 0; e < 4; ++e) acc[i][j][e] = 0.f;

    prefetch(0, 0); cp_commit();
    const int NCH = IN_F/KC;  // 8
    for (int kc = 0; kc < NCH; ++kc) {
        if (kc+1 < NCH) { prefetch(kc+1, (kc+1)&1); cp_commit(); cp_wait1(); }
        else            { cp_wait0(); }
        __syncthreads();
        const unsigned* A_h = (const unsigned*)(Ah + (kc&1)*128*HS);
        const unsigned* A_l = (const unsigned*)(Al + (kc&1)*128*HS);
        const unsigned* B_h = (const unsigned*)(Bh + (kc&1)*128*HS);
        const unsigned* B_l = (const unsigned*)(Bl + (kc&1)*128*HS);
        #pragma unroll
        for (int kk = 0; kk < 2; ++kk) {       // two k16 steps
            int base = kk*8;                   // u32 units (HS/2 = 20 per row)
            unsigned ah[2][4], al[2][4];
            #pragma unroll
            for (int mi = 0; mi < 2; ++mi) {
                int r0 = (wm + mi*16 + gid)*20;
                int r1 = r0 + 8*20;
                ah[mi][0] = A_h[r0 + base + tig];     al[mi][0] = A_l[r0 + base + tig];
                ah[mi][1] = A_h[r1 + base + tig];     al[mi][1] = A_l[r1 + base + tig];
                ah[mi][2] = A_h[r0 + base + 4 + tig]; al[mi][2] = A_l[r0 + base + 4 + tig];
                ah[mi][3] = A_h[r1 + base + 4 + tig]; al[mi][3] = A_l[r1 + base + 4 + tig];
            }
            #pragma unroll
            for (int ni = 0; ni < 8; ++ni) {
                int n0 = (wn + ni*8 + gid)*20;
                unsigned bh[2], bl[2];
                bh[0] = B_h[n0 + base + tig];     bh[1] = B_h[n0 + base + 4 + tig];
                bl[0] = B_l[n0 + base + tig];     bl[1] = B_l[n0 + base + 4 + tig];
                #pragma unroll
                for (int mi = 0; mi < 2; ++mi) {
                    mma_bf16(acc[mi][ni], ah[mi], bl);
                    mma_bf16(acc[mi][ni], al[mi], bh);
                    mma_bf16(acc[mi][ni], ah[mi], bh);
                }
            }
        }
        __syncthreads();
    }

    // epilogue: bias+lrelu -> smem fp32 -> coalesced split stores
    int zp = s*HN + nt;
    float* Cs = (float*)smc;  // 128x132
    #pragma unroll
    for (int mi = 0; mi < 2; ++mi)
        #pragma unroll
        for (int ni = 0; ni < 8; ++ni)
            #pragma unroll
            for (int e = 0; e < 4; ++e) {
                int r = wm + mi*16 + gid + ((e >= 2) ? 8 : 0);
                int c = wn + ni*8 + 2*tig + (e & 1);
                Cs[r*132 + c] = lrelu_f(acc[mi][ni][e] + fcb[zp*H + c]);
            }
    __syncthreads();
    #pragma unroll
    for (int t = 0; t < 16; ++t) {
        int idx = tid + t*256;                 // f4 index, 4096 total
        int rr = idx >> 5, c4 = (idx & 31)*4;
        float4 v = *(const float4*)(Cs + rr*132 + c4);
        int gr = mt*128 + rr;
        if (gr < BM_) {
            size_t base = ((size_t)zp*BM_ + gr)*H + c4;
            __nv_bfloat16 h0,h1,h2_,h3,l0,l1,l2,l3;
            split_bf(v.x,h0,l0); split_bf(v.y,h1,l1);
            split_bf(v.z,h2_,l2); split_bf(v.w,h3,l3);
            __nv_bfloat162 ph0 = {h0,h1}, ph1 = {h2_,h3};
            __nv_bfloat162 pl0 = {l0,l1}, pl1 = {l2,l3};
            uint2 uh, ul;
            uh.x = *(unsigned*)&ph0; uh.y = *(unsigned*)&ph1;
            ul.x = *(unsigned*)&pl0; ul.y = *(unsigned*)&pl1;
            *(uint2*)(yh + base) = uh;
            *(uint2*)(yl + base) = ul;
        } else {
            *(float4*)(xsh + ((size_t)zp*Bq + (gr - BM_))*H + c4) = v;
        }
    }
}

// ================= fused h1/vh GEMM + attention (bf16-split) =================
// Per block: pair z, 128 rows (8 targets). 128x256 GEMM (B = [ckw | v_w]),
// then bilinear score, softmax over M=16, lrelu-weighted V sum, residual.
#define FU_GEMM_BYTES ((2*128*HS + 2*256*HS)*2*2)
#define FU_EPI_BYTES  ((128*132 + 128*132 + 8*128 + 128 + 128)*4)
#define FU_SMEM       (FU_EPI_BYTES > FU_GEMM_BYTES ? FU_EPI_BYTES : FU_GEMM_BYTES)
__global__ __launch_bounds__(512,1) void fused_attn(
    const __nv_bfloat16* __restrict__ yhg, const __nv_bfloat16* __restrict__ ylg,
    const __nv_bfloat16* __restrict__ ckh, const __nv_bfloat16* __restrict__ ckl,
    const float* __restrict__ ckb,
    const __nv_bfloat16* __restrict__ vwh, const __nv_bfloat16* __restrict__ vwl,
    const float* __restrict__ vb,  const float* __restrict__ wh2,
    const float* __restrict__ xsh, float* __restrict__ sout)
{
    extern __shared__ __align__(16) char smc[];
    float* sm = (float*)smc;
    __nv_bfloat16* Ah = (__nv_bfloat16*)smc;       // [2][128*HS]
    __nv_bfloat16* Al = Ah + 2*128*HS;
    __nv_bfloat16* Bh = Al + 2*128*HS;             // [2][256*HS]
    __nv_bfloat16* Bl = Bh + 2*256*HS;
    int mt = blockIdx.x, z = blockIdx.y;
    int tid = threadIdx.x;

    const __nv_bfloat16* Agh = yhg + ((size_t)z*BM_ + mt*128)*H;
    const __nv_bfloat16* Agl = ylg + ((size_t)z*BM_ + mt*128)*H;
    size_t wkb = (size_t)z*H*H;

    auto prefetch = [&](int kc, int buf) {
        {
            int r = tid >> 2, seg = (tid & 3)*8;   // 512 transfers A
            int so = buf*128*HS + r*HS + seg;
            size_t ga = (size_t)r*H + kc*KC + seg;
            cpa16(Ah + so, Agh + ga);
            cpa16(Al + so, Agl + ga);
        }
        #pragma unroll
        for (int i = 0; i < 2; ++i) {              // 1024 transfers B
            int idx = tid + i*512;
            int n = idx >> 2, seg = (idx & 3)*8;
            int so = buf*256*HS + n*HS + seg;
            const __nv_bfloat16* srch, *srcl;
            if (n < 128) { srch = ckh + wkb + (size_t)n*H;        srcl = ckl + wkb + (size_t)n*H; }
            else         { srch = vwh + wkb + (size_t)(n-128)*H;  srcl = vwl + wkb + (size_t)(n-128)*H; }
            cpa16(Bh + so, srch + kc*KC + seg);
            cpa16(Bl + so, srcl + kc*KC + seg);
        }
    };

    int w = tid >> 5, lane = tid & 31, gid = lane >> 2, tig = lane & 3;
    int wm = (w & 3)*32, wn = (w >> 2)*64;
    float acc[2][8][4];
    #pragma unroll
    for (int i = 0; i < 2; ++i)
        #pragma unroll
        for (int j = 0; j < 8; ++j)
            #pragma unroll
            for (int e = 0; e < 4; ++e) acc[i][j][e] = 0.f;

    prefetch(0, 0); cp_commit();
    const int NCH = H/KC;  // 4
    for (int kc = 0; kc < NCH; ++kc) {
        if (kc+1 < NCH) { prefetch(kc+1, (kc+1)&1); cp_commit(); cp_wait1(); }
        else            { cp_wait0(); }
        __syncthreads();
        const unsigned* A_h = (const unsigned*)(Ah + (kc&1)*128*HS);
        const unsigned* A_l = (const unsigned*)(Al + (kc&1)*128*HS);
        const unsigned* B_h = (const unsigned*)(Bh + (kc&1)*256*HS);
        const unsigned* B_l = (const unsigned*)(Bl + (kc&1)*256*HS);
        #pragma unroll
        for (int kk = 0; kk < 2; ++kk) {
            int base = kk*8;
            unsigned ah[2][4], al[2][4];
            #pragma unroll
            for (int mi = 0; mi < 2; ++mi) {
                int r0 = (wm + mi*16 + gid)*20;
                int r1 = r0 + 8*20;
                ah[mi][0] = A_h[r0 + base + tig];     al[mi][0] = A_l[r0 + base + tig];
                ah[mi][1] = A_h[r1 + base + tig];     al[mi][1] = A_l[r1 + base + tig];
                ah[mi][2] = A_h[r0 + base + 4 + tig]; al[mi][2] = A_l[r0 + base + 4 + tig];
                ah[mi][3] = A_h[r1 + base + 4 + tig]; al[mi][3] = A_l[r1 + base + 4 + tig];
            }
            #pragma unroll
            for (int ni = 0; ni < 8; ++ni) {
                int n0 = (wn + ni*8 + gid)*20;
                unsigned bh[2], bl[2];
                bh[0] = B_h[n0 + base + tig];     bh[1] = B_h[n0 + base + 4 + tig];
                bl[0] = B_l[n0 + base + tig];     bl[1] = B_l[n0 + base + 4 + tig];
                #pragma unroll
                for (int mi = 0; mi < 2; ++mi) {
                    mma_bf16(acc[mi][ni], ah[mi], bl);
                    mma_bf16(acc[mi][ni], al[mi], bh);
                    mma_bf16(acc[mi][ni], ah[mi], bh);
                }
            }
        }
        __syncthreads();
    }

    // epilogue smem (aliases GEMM buffers; all compute done)
    float* SP  = sm;                 // [128][132]  h1 (lrelu+bias)
    float* SV  = SP + 128*132;       // [128][132]  vh (+bias)
    float* SW  = SV + 128*132;       // [8][128]    wh2 rows
    float* SSC = SW + 8*128;         // [128] scores
    float* SE  = SSC + 128;          // [128] softmax weights

    #pragma unroll
    for (int mi = 0; mi < 2; ++mi)
        #pragma unroll
        for (int ni = 0; ni < 8; ++ni)
            #pragma unroll
            for (int e = 0; e < 4; ++e) {
                int r = wm + mi*16 + gid + ((e >= 2) ? 8 : 0);
                int c = wn + ni*8 + 2*tig + (e & 1);
                float v = acc[mi][ni][e];
                if (c < 128) SP[r*132 + c] = lrelu_f(v + ckb[z*H + c]);
                else         SV[r*132 + (c-128)] = v + vb[z*H + (c-128)];
            }
    #pragma unroll
    for (int t = 0; t < 2; ++t) {
        int idx = tid + t*512;       // 1024 = 8 b x 128
        int bl = idx >> 7, o = idx & 127;
        SW[idx] = wh2[((size_t)z*Bq + mt*8 + bl)*H + o];
    }
    __syncthreads();

    // scores: warp w -> rows w*8 .. w*8+7
    #pragma unroll
    for (int i = 0; i < 8; ++i) {
        int rr = w*8 + i;
        const float* wrow = SW + (rr >> 4)*128;
        float p = 0.f;
        #pragma unroll
        for (int o = 0; o < 128; o += 32) p += SP[rr*132 + o + lane]*wrow[o + lane];
        #pragma unroll
        for (int d_ = 16; d_ > 0; d_ >>= 1) p += __shfl_xor_sync(0xffffffffu, p, d_);
        if (lane == 0) SSC[rr] = p;
    }
    __syncthreads();
    if (tid < 8) {
        float mx = -1e30f;
        #pragma unroll
        for (int m = 0; m < M; ++m) mx = fmaxf(mx, SSC[tid*M + m]);
        float es[M], sum = 0.f;
        #pragma unroll
        for (int m = 0; m < M; ++m) { es[m] = expf(SSC[tid*M + m] - mx); sum += es[m]; }
        float inv = 1.f/sum;
        #pragma unroll
        for (int m = 0; m < M; ++m) SE[tid*M + m] = es[m]*inv;
    }
    __syncthreads();

    int s = z/HN, hh = z%HN;
    #pragma unroll
    for (int t = 0; t < 2; ++t) {
        int idx = tid + t*512;
        int bl = idx >> 7, o = idx & 127;
        float a = 0.f;
        #pragma unroll
        for (int m = 0; m < M; ++m) {
            float v = SV[(bl*M + m)*132 + o]*SE[bl*M + m];
            a += (v >= 0.f) ? v : ALPHA*v;
        }
        int b = mt*8 + bl;
        sout[((size_t)s*Bq + b)*D + hh*H + o] =
            0.5f*(xsh[((size_t)z*Bq + b)*H + o] + a);
    }
}

// ---------------- small fp32 GEMM for h2 / wh2 ----------------
__global__ __launch_bounds__(256) void gemm128(
    const float* __restrict__ Abase, const float* __restrict__ Wbase,
    const float* __restrict__ biasBase, float* __restrict__ Cbase,
    int Mrows, int doLrelu, int wKmap)
{
    int mt = blockIdx.x, z = blockIdx.y;
    int wz = z;
    if (wKmap) wz = c_kofs[z/HN]*HN + (z % HN);
    const float* A = Abase + (size_t)z*Mrows*H;
    const float* W = Wbase + (size_t)wz*H*H;
    float*       C = Cbase + (size_t)z*Mrows*H;
    int tid = threadIdx.x;
    __shared__ float As[8][132];
    __shared__ float Bs[8][132];
    int tx = tid & 15, ty = tid >> 4;
    int la_r = tid >> 1, la_k = (tid & 1)*4;
    float acc[8][8];
    #pragma unroll
    for (int i = 0; i < 8; ++i)
        #pragma unroll
        for (int j = 0; j < 8; ++j) acc[i][j] = 0.f;
    const float* arow = A + ((size_t)mt*128 + la_r)*H + la_k;
    const float* brow = W + (size_t)la_r*H + la_k;
    for (int k0 = 0; k0 < H; k0 += 8) {
        float4 av = *(const float4*)(arow + k0);
        float4 bv = *(const float4*)(brow + k0);
        As[la_k+0][la_r]=av.x; As[la_k+1][la_r]=av.y; As[la_k+2][la_r]=av.z; As[la_k+3][la_r]=av.w;
        Bs[la_k+0][la_r]=bv.x; Bs[la_k+1][la_r]=bv.y; Bs[la_k+2][la_r]=bv.z; Bs[la_k+3][la_r]=bv.w;
        __syncthreads();
        #pragma unroll
        for (int kk = 0; kk < 8; ++kk) {
            float4 a0 = *(const float4*)&As[kk][ty*8];
            float4 a1 = *(const float4*)&As[kk][ty*8+4];
            float4 b0 = *(const float4*)&Bs[kk][tx*8];
            float4 b1 = *(const float4*)&Bs[kk][tx*8+4];
            float ra[8] = {a0.x,a0.y,a0.z,a0.w,a1.x,a1.y,a1.z,a1.w};
            float rb[8] = {b0.x,b0.y,b0.z,b0.w,b1.x,b1.y,b1.z,b1.w};
            #pragma unroll
            for (int i = 0; i < 8; ++i)
                #pragma unroll
                for (int j = 0; j < 8; ++j) acc[i][j] += ra[i]*rb[j];
        }
        __syncthreads();
    }
    float bj[8];
    #pragma unroll
    for (int j = 0; j < 8; ++j) bj[j] = biasBase ? biasBase[z*H + tx*8 + j] : 0.f;
    #pragma unroll
    for (int i = 0; i < 8; ++i) {
        int r = mt*128 + ty*8 + i;
        #pragma unroll
        for (int j = 0; j < 8; ++j) {
            int o = tx*8 + j;
            float v = acc[i][j] + bj[j];
            if (doLrelu) v = v >= 0.f ? v : ALPHA*v;
            C[(size_t)r*H + o] = v;
        }
    }
}

// ---------------- semantic attention ----------------
template<int P>
__global__ __launch_bounds__(128) void semantic(
    const float* __restrict__ zin, const float* __restrict__ p1w,
    const float* __restrict__ p1b, const float* __restrict__ p2w,
    float* __restrict__ outp, int in_pstride, int in_bstride, int out_bstride)
{
    int b0 = blockIdx.x*4, tid = threadIdx.x;
    __shared__ float zs[4][P][D];
    int tot = 4*P*D;
    for (int idx = tid; idx < tot; idx += 128) {
        int d = idx % D; int rp = idx / D; int p = rp % P; int bl = rp / P;
        zs[bl][p][d] = zin[(size_t)(b0+bl)*in_bstride + (size_t)p*in_pstride + d];
    }
    __syncthreads();
    float acc[4][P];
    #pragma unroll
    for (int bl = 0; bl < 4; ++bl)
        #pragma unroll
        for (int p = 0; p < P; ++p) acc[bl][p] = 0.f;
    const float* wrow = p1w + (size_t)tid*D;
    for (int d = 0; d < D; ++d) {
        float wv = wrow[d];
        #pragma unroll
        for (int bl = 0; bl < 4; ++bl)
            #pragma unroll
            for (int p = 0; p < P; ++p) acc[bl][p] += wv*zs[bl][p][d];
    }
    float bias = p1b[tid], p2 = p2w[tid];
    __shared__ float sred[4*P][132];
    __shared__ float ssc[4*P];
    #pragma unroll
    for (int bl = 0; bl < 4; ++bl)
        #pragma unroll
        for (int p = 0; p < P; ++p)
            sred[bl*P+p][tid] = tanhf(acc[bl][p] + bias)*p2;
    __syncthreads();
    if (tid < 4*P) {
        float s_ = 0.f;
        for (int o = 0; o < H; ++o) s_ += sred[tid][o];
        ssc[tid] = s_;
    }
    __syncthreads();
    #pragma unroll
    for (int bl = 0; bl < 4; ++bl) {
        float mx = -1e30f;
        #pragma unroll
        for (int p = 0; p < P; ++p) mx = fmaxf(mx, ssc[bl*P+p]);
        float e[P]; float esum = 0.f;
        #pragma unroll
        for (int p = 0; p < P; ++p) { e[p] = expf(ssc[bl*P+p] - mx); esum += e[p]; }
        float inv = 1.f/esum;
        for (int d = tid; d < D; d += 128) {
            float o_ = 0.f;
            #pragma unroll
            for (int p = 0; p < P; ++p) o_ += e[p]*zs[bl][p][d];
            outp[(size_t)(b0+bl)*out_bstride + d] = o_*inv;
        }
    }
}

extern "C" void kernel_launch(void* const* d_in, const int* in_sizes, int n_in,
                              void* d_out, int out_size)
{
    const float* x     = (const float*)d_in[0];
    const int*   tgt   = (const int*)  d_in[1];
    const int*   neigh = (const int*)  d_in[2];
    const float* fc_w  = (const float*)d_in[3];
    const float* fc_b  = (const float*)d_in[4];
    const float* q_w   = (const float*)d_in[5];
    const float* q_b   = (const float*)d_in[6];
    const float* k_w   = (const float*)d_in[7];
    const float* k_b   = (const float*)d_in[8];
    const float* v_w   = (const float*)d_in[9];
    const float* v_b   = (const float*)d_in[10];
    const float* att_W = (const float*)d_in[11];
    const float* a1w   = (const float*)d_in[12];
    const float* a1b   = (const float*)d_in[13];
    const float* a2w   = (const float*)d_in[14];
    const float* a2b   = (const float*)d_in[15];
    const float* ip1w  = (const float*)d_in[16];
    const float* ip1b  = (const float*)d_in[17];
    const float* ip2w  = (const float*)d_in[18];
    const float* bp1w  = (const float*)d_in[19];
    const float* bp1b  = (const float*)d_in[20];
    const float* bp2w  = (const float*)d_in[21];
    float* out = (float*)d_out;

    __nv_bfloat16 *xhi,*xlo,*fwh,*fwl,*vwh,*vwl,*ckwh,*ckwl,*yh,*yl;
    float *ckb,*cqw,*cqb,*xsh,*h2,*wh2,*sout,*mp;
    cudaGetSymbolAddress((void**)&xhi,  g_xhi);
    cudaGetSymbolAddress((void**)&xlo,  g_xlo);
    cudaGetSymbolAddress((void**)&fwh,  g_fwh);
    cudaGetSymbolAddress((void**)&fwl,  g_fwl);
    cudaGetSymbolAddress((void**)&vwh,  g_vwh);
    cudaGetSymbolAddress((void**)&vwl,  g_vwl);
    cudaGetSymbolAddress((void**)&ckwh, g_ckwh);
    cudaGetSymbolAddress((void**)&ckwl, g_ckwl);
    cudaGetSymbolAddress((void**)&ckb,  g_ckb);
    cudaGetSymbolAddress((void**)&cqw,  g_cqw);
    cudaGetSymbolAddress((void**)&cqb,  g_cqb);
    cudaGetSymbolAddress((void**)&xsh,  g_xsh);
    cudaGetSymbolAddress((void**)&yh,   g_yh);
    cudaGetSymbolAddress((void**)&yl,   g_yl);
    cudaGetSymbolAddress((void**)&h2,   g_h2);
    cudaGetSymbolAddress((void**)&wh2,  g_wh2);
    cudaGetSymbolAddress((void**)&sout, g_sout);
    cudaGetSymbolAddress((void**)&mp,   g_mp);

    static int smem_set = 0;
    if (!smem_set) {
        cudaFuncSetAttribute(fc_bf16,    cudaFuncAttributeMaxDynamicSharedMemorySize, FC2_SMEM);
        cudaFuncSetAttribute(fused_attn, cudaFuncAttributeMaxDynamicSharedMemorySize, FU_SMEM);
        smem_set = 1;
    }

    // 0. precompute bf16 hi/lo splits (once per launch; input-dependent)
    split2<<<(NN*IN_F + 255)/256, 256>>>(x,   xhi, xlo, NN*IN_F);
    split2<<<(S*4*H*IN_F + 255)/256, 256>>>(fc_w, fwh, fwl, S*4*H*IN_F);
    split2<<<(PAIRS*H*H + 255)/256, 256>>>(v_w,  vwh, vwl, PAIRS*H*H);

    // 1. fold attention-layer weights into k/q projections
    combine_w_b<<<dim3(H, PAIRS), H>>>(a1w, a1b, k_w, k_b, ckwh, ckwl, ckb);
    combine_w  <<<dim3(H, PAIRS), H>>>(a2w, a2b, q_w, q_b, cqw, cqb);

    // 2. shared fc + leakyrelu on gathered neighbors + targets (bf16-split TC)
    fc_bf16<<<dim3(R_/128, 4, S), 256, FC2_SMEM>>>(xhi, xlo, neigh, tgt, fwh, fwl,
                                                   fc_b, yh, yl, xsh);

    // 3. h2 = lrelu(xsh @ cq^T + cqb);  wh2 = h2 @ att_W^T  (small)
    gemm128<<<dim3(Bq/128, PAIRS), 256>>>(xsh, cqw, cqb, h2, Bq, 1, 0);
    gemm128<<<dim3(Bq/128, PAIRS), 256>>>(h2, att_W, nullptr, wh2, Bq, 0, 1);

    // 4. fused h1/vh GEMM + neighbor attention + residual (bf16-split TC)
    fused_attn<<<dim3(BM_/128, PAIRS), 512, FU_SMEM>>>(yh, yl, ckwh, ckwl, ckb,
                                                       vwh, vwl, v_b, wh2, xsh, sout);

    // 5. semantic attention within each metapath
    semantic<2><<<Bq/4, 128>>>(sout,          ip1w,       ip1b,     ip2w,     mp,     Bq*D, D, KM*D);
    semantic<3><<<Bq/4, 128>>>(sout + 2*Bq*D, ip1w + H*D, ip1b + H, ip2w + H, mp + D, Bq*D, D, KM*D);

    // 6. semantic attention between metapaths -> final output
    semantic<2><<<Bq/4, 128>>>(mp, bp1w, bp1b, bp2w, out, D, KM*D, D);
}

// round 5
// speedup vs baseline: 2.2804x; 1.1307x over previous
#include <cuda_runtime.h>
#include <cuda_bf16.h>
#include <math.h>

#define NN    20000
#define IN_F  256
#define H     128
#define HN    4
#define S     5
#define KM    2
#define Bq    1024
#define M     16
#define D     512
#define ALPHA 0.2f
#define BM_   (Bq*M)      /* 16384 */
#define R_    (BM_ + Bq)  /* 17408 */
#define PAIRS (S*HN)      /* 20 */

#define KC    32          /* K halves per pipeline stage */
#define HS    40          /* smem row stride in halves (KC + 8 pad) */

__constant__ int c_kofs[S] = {0,0,1,1,1};

// ---------------- scratch ----------------
__device__ __nv_bfloat16 g_xhi[NN*IN_F];
__device__ __nv_bfloat16 g_xlo[NN*IN_F];
__device__ __nv_bfloat16 g_fwh[S*4*H*IN_F];
__device__ __nv_bfloat16 g_fwl[S*4*H*IN_F];
__device__ __nv_bfloat16 g_vwh[PAIRS*H*H];
__device__ __nv_bfloat16 g_vwl[PAIRS*H*H];
__device__ __nv_bfloat16 g_awh[KM*HN*H*H];
__device__ __nv_bfloat16 g_awl[KM*HN*H*H];
__device__ __nv_bfloat16 g_ckwh[PAIRS*H*H];
__device__ __nv_bfloat16 g_ckwl[PAIRS*H*H];
__device__ float g_ckb[PAIRS*H];
__device__ __nv_bfloat16 g_cqwh[PAIRS*H*H];
__device__ __nv_bfloat16 g_cqwl[PAIRS*H*H];
__device__ float g_cqb[PAIRS*H];
__device__ float g_xsh[PAIRS*Bq*H];
__device__ __nv_bfloat16 g_xshh[PAIRS*Bq*H];
__device__ __nv_bfloat16 g_xshl[PAIRS*Bq*H];
__device__ __nv_bfloat16 g_yh[(size_t)PAIRS*BM_*H];
__device__ __nv_bfloat16 g_yl[(size_t)PAIRS*BM_*H];
__device__ float g_wh2[PAIRS*Bq*H];
__device__ float g_sout[S*Bq*D];
__device__ float g_mp[Bq*KM*D];

// ---------------- helpers ----------------
__device__ __forceinline__ void mma_bf16(float* d, const unsigned* a, const unsigned* b) {
    asm volatile(
      "mma.sync.aligned.m16n8k16.row.col.f32.bf16.bf16.f32 "
      "{%0,%1,%2,%3}, {%4,%5,%6,%7}, {%8,%9}, {%0,%1,%2,%3};\n"
      : "+f"(d[0]), "+f"(d[1]), "+f"(d[2]), "+f"(d[3])
      : "r"(a[0]), "r"(a[1]), "r"(a[2]), "r"(a[3]), "r"(b[0]), "r"(b[1]));
}
__device__ __forceinline__ void split_bf(float x, __nv_bfloat16& h, __nv_bfloat16& l) {
    h = __float2bfloat16_rn(x);
    l = __float2bfloat16_rn(x - __bfloat162float(h));
}
__device__ __forceinline__ void cpa16(void* dst, const void* src) {
    unsigned d = (unsigned)__cvta_generic_to_shared(dst);
    asm volatile("cp.async.cg.shared.global [%0], [%1], 16;\n" :: "r"(d), "l"(src));
}
__device__ __forceinline__ void cp_commit() { asm volatile("cp.async.commit_group;\n"); }
__device__ __forceinline__ void cp_wait1() { asm volatile("cp.async.wait_group 1;\n"); }
__device__ __forceinline__ void cp_wait0() { asm volatile("cp.async.wait_group 0;\n"); }
__device__ __forceinline__ float lrelu_f(float v) { return v >= 0.f ? v : ALPHA*v; }

// ---------------- generic fp32 -> bf16 hi/lo split ----------------
__global__ void split2(const float* __restrict__ in, __nv_bfloat16* __restrict__ hi,
                       __nv_bfloat16* __restrict__ lo, int n)
{
    int i = blockIdx.x*256 + threadIdx.x;
    if (i < n) split_bf(in[i], hi[i], lo[i]);
}

// ---------------- combined weights: cw[o,i] = sum_j a[kz][o,j] w[z][j,i] ----------------
// grid (4, PAIRS), block 256. 32-row output tile, K=128 chunked by 32.
__global__ __launch_bounds__(256) void combine_gemm(
    const float* __restrict__ aw, const float* __restrict__ ab,
    const float* __restrict__ w,  const float* __restrict__ wb,
    __nv_bfloat16* __restrict__ cwh, __nv_bfloat16* __restrict__ cwl,
    float* __restrict__ cb)
{
    int ot = blockIdx.x, z = blockIdx.y, tid = threadIdx.x;
    int kz = c_kofs[z/HN]*HN + (z % HN);
    const float* A = aw + ((size_t)kz*H + ot*32)*H;   // [32][128]
    const float* W = w + (size_t)z*H*H;               // [128][128]
    __shared__ float sa[32][36];
    __shared__ float sw[32][132];
    int tx = tid & 15, ty = tid >> 4;                 // 16x16
    float acc[2][8];
    #pragma unroll
    for (int r = 0; r < 2; ++r)
        #pragma unroll
        for (int c = 0; c < 8; ++c) acc[r][c] = 0.f;
    for (int kc = 0; kc < 4; ++kc) {
        {   // load A chunk 32x32
            int r = tid >> 3, c4 = (tid & 7)*4;
            *(float4*)&sa[r][c4] = *(const float4*)(A + r*H + kc*32 + c4);
        }
        #pragma unroll
        for (int i = 0; i < 4; ++i) {  // load W chunk 32x128
            int idx = tid + i*256;
            int r = idx >> 5, c4 = (idx & 31)*4;
            *(float4*)&sw[r][c4] = *(const float4*)(W + (kc*32 + r)*H + c4);
        }
        __syncthreads();
        #pragma unroll 8
        for (int j = 0; j < 32; ++j) {
            float a0 = sa[ty*2][j], a1 = sa[ty*2+1][j];
            #pragma unroll
            for (int c = 0; c < 8; ++c) {
                float wv = sw[j][tx*8 + c];
                acc[0][c] += a0*wv;
                acc[1][c] += a1*wv;
            }
        }
        __syncthreads();
    }
    #pragma unroll
    for (int r = 0; r < 2; ++r)
        #pragma unroll
        for (int c = 0; c < 8; ++c) {
            size_t idx = ((size_t)z*H + ot*32 + ty*2 + r)*H + tx*8 + c;
            split_bf(acc[r][c], cwh[idx], cwl[idx]);
        }
    if (tid < 32) {
        int o = ot*32 + tid;
        float bacc = ab[kz*H + o];
        const float* arow = aw + ((size_t)kz*H + o)*H;
        const float* brow = wb + z*H;
        for (int j = 0; j < H; ++j) bacc += arow[j]*brow[j];
        cb[z*H + o] = bacc;
    }
}

// ================= fc GEMM (bf16-split tensor core, gather) =================
#define FC2_SMEM (8*128*HS*2 + 512)
__global__ __launch_bounds__(256,2) void fc_bf16(
    const __nv_bfloat16* __restrict__ xh, const __nv_bfloat16* __restrict__ xl,
    const int* __restrict__ neigh, const int* __restrict__ tgt,
    const __nv_bfloat16* __restrict__ fwh, const __nv_bfloat16* __restrict__ fwl,
    const float* __restrict__ fcb,
    __nv_bfloat16* __restrict__ yh, __nv_bfloat16* __restrict__ yl,
    float* __restrict__ xsh,
    __nv_bfloat16* __restrict__ xshh, __nv_bfloat16* __restrict__ xshl)
{
    extern __shared__ __align__(16) char smc[];
    __nv_bfloat16* Ah = (__nv_bfloat16*)smc;       // [2][128*HS]
    __nv_bfloat16* Al = Ah + 2*128*HS;
    __nv_bfloat16* Bh = Al + 2*128*HS;
    __nv_bfloat16* Bl = Bh + 2*128*HS;
    int* rows = (int*)(Bl + 2*128*HS);
    int mt = blockIdx.x, nt = blockIdx.y, s = blockIdx.z;
    int tid = threadIdx.x;
    if (tid < 128) {
        int r = mt*128 + tid;
        rows[tid] = (r < BM_) ? neigh[s*BM_ + r] : tgt[r - BM_];
    }
    __syncthreads();
    size_t wb = ((size_t)s*512 + nt*128)*IN_F;

    auto prefetch = [&](int kc, int buf) {
        #pragma unroll
        for (int i = 0; i < 2; ++i) {
            int idx = tid + i*256;
            int r = idx >> 2, seg = (idx & 3)*8;
            int so = buf*128*HS + r*HS + seg;
            size_t ga = (size_t)rows[r]*IN_F + kc*KC + seg;
            size_t gb = wb + (size_t)r*IN_F + kc*KC + seg;
            cpa16(Ah + so, xh + ga);
            cpa16(Al + so, xl + ga);
            cpa16(Bh + so, fwh + gb);
            cpa16(Bl + so, fwl + gb);
        }
    };

    int w = tid >> 5, lane = tid & 31, gid = lane >> 2, tig = lane & 3;
    int wm = (w & 3)*32, wn = (w >> 2)*64;
    float acc[2][8][4];
    #pragma unroll
    for (int i = 0; i < 2; ++i)
        #pragma unroll
        for (int j = 0; j < 8; ++j)
            #pragma unroll
            for (int e = 0; e < 4; ++e) acc[i][j][e] = 0.f;

    prefetch(0, 0); cp_commit();
    const int NCH = IN_F/KC;  // 8
    for (int kc = 0; kc < NCH; ++kc) {
        if (kc+1 < NCH) { prefetch(kc+1, (kc+1)&1); cp_commit(); cp_wait1(); }
        else            { cp_wait0(); }
        __syncthreads();
        const unsigned* A_h = (const unsigned*)(Ah + (kc&1)*128*HS);
        const unsigned* A_l = (const unsigned*)(Al + (kc&1)*128*HS);
        const unsigned* B_h = (const unsigned*)(Bh + (kc&1)*128*HS);
        const unsigned* B_l = (const unsigned*)(Bl + (kc&1)*128*HS);
        #pragma unroll
        for (int kk = 0; kk < 2; ++kk) {
            int base = kk*8;
            unsigned ah[2][4], al[2][4];
            #pragma unroll
            for (int mi = 0; mi < 2; ++mi) {
                int r0 = (wm + mi*16 + gid)*20;
                int r1 = r0 + 8*20;
                ah[mi][0] = A_h[r0 + base + tig];     al[mi][0] = A_l[r0 + base + tig];
                ah[mi][1] = A_h[r1 + base + tig];     al[mi][1] = A_l[r1 + base + tig];
                ah[mi][2] = A_h[r0 + base + 4 + tig]; al[mi][2] = A_l[r0 + base + 4 + tig];
                ah[mi][3] = A_h[r1 + base + 4 + tig]; al[mi][3] = A_l[r1 + base + 4 + tig];
            }
            #pragma unroll
            for (int ni = 0; ni < 8; ++ni) {
                int n0 = (wn + ni*8 + gid)*20;
                unsigned bh[2], bl[2];
                bh[0] = B_h[n0 + base + tig];     bh[1] = B_h[n0 + base + 4 + tig];
                bl[0] = B_l[n0 + base + tig];     bl[1] = B_l[n0 + base + 4 + tig];
                #pragma unroll
                for (int mi = 0; mi < 2; ++mi) {
                    mma_bf16(acc[mi][ni], ah[mi], bl);
                    mma_bf16(acc[mi][ni], al[mi], bh);
                    mma_bf16(acc[mi][ni], ah[mi], bh);
                }
            }
        }
        __syncthreads();
    }

    int zp = s*HN + nt;
    float* Cs = (float*)smc;  // 128x132
    #pragma unroll
    for (int mi = 0; mi < 2; ++mi)
        #pragma unroll
        for (int ni = 0; ni < 8; ++ni)
            #pragma unroll
            for (int e = 0; e < 4; ++e) {
                int r = wm + mi*16 + gid + ((e >= 2) ? 8 : 0);
                int c = wn + ni*8 + 2*tig + (e & 1);
                Cs[r*132 + c] = lrelu_f(acc[mi][ni][e] + fcb[zp*H + c]);
            }
    __syncthreads();
    #pragma unroll
    for (int t = 0; t < 16; ++t) {
        int idx = tid + t*256;
        int rr = idx >> 5, c4 = (idx & 31)*4;
        float4 v = *(const float4*)(Cs + rr*132 + c4);
        int gr = mt*128 + rr;
        __nv_bfloat16 h0,h1,h2_,h3,l0,l1,l2,l3;
        split_bf(v.x,h0,l0); split_bf(v.y,h1,l1);
        split_bf(v.z,h2_,l2); split_bf(v.w,h3,l3);
        __nv_bfloat162 ph0 = {h0,h1}, ph1 = {h2_,h3};
        __nv_bfloat162 pl0 = {l0,l1}, pl1 = {l2,l3};
        uint2 uh, ul;
        uh.x = *(unsigned*)&ph0; uh.y = *(unsigned*)&ph1;
        ul.x = *(unsigned*)&pl0; ul.y = *(unsigned*)&pl1;
        if (gr < BM_) {
            size_t base = ((size_t)zp*BM_ + gr)*H + c4;
            *(uint2*)(yh + base) = uh;
            *(uint2*)(yl + base) = ul;
        } else {
            size_t base = ((size_t)zp*Bq + (gr - BM_))*H + c4;
            *(float4*)(xsh + base) = v;
            *(uint2*)(xshh + base) = uh;
            *(uint2*)(xshl + base) = ul;
        }
    }
}

// ================= qk_fused: wh2 = (lrelu(xsh@cq^T+cqb)) @ attW^T =================
// grid (8, PAIRS), block 256. Full K=128 resident; two chained split GEMMs.
#define QKS   136                      /* row stride in halves */
#define QK_SMEM (4*128*QKS*2)
__global__ __launch_bounds__(256,1) void qk_fused(
    const __nv_bfloat16* __restrict__ xshh, const __nv_bfloat16* __restrict__ xshl,
    const __nv_bfloat16* __restrict__ cqh, const __nv_bfloat16* __restrict__ cql,
    const float* __restrict__ cqb,
    const __nv_bfloat16* __restrict__ awh, const __nv_bfloat16* __restrict__ awl,
    float* __restrict__ wh2)
{
    extern __shared__ __align__(16) char smc[];
    __nv_bfloat16* Axh = (__nv_bfloat16*)smc;   // [128*QKS]
    __nv_bfloat16* Axl = Axh + 128*QKS;
    __nv_bfloat16* Bh  = Axl + 128*QKS;
    __nv_bfloat16* Bl  = Bh + 128*QKS;
    int mt = blockIdx.x, z = blockIdx.y;
    int tid = threadIdx.x;
    int kz = c_kofs[z/HN]*HN + (z % HN);

    const __nv_bfloat16* Agh = xshh + ((size_t)z*Bq + mt*128)*H;
    const __nv_bfloat16* Agl = xshl + ((size_t)z*Bq + mt*128)*H;
    const __nv_bfloat16* Bgh = cqh + (size_t)z*H*H;
    const __nv_bfloat16* Bgl = cql + (size_t)z*H*H;

    // load A (xsh split) and B (cq split): 128x128 halves each
    #pragma unroll
    for (int i = 0; i < 8; ++i) {
        int idx = tid + i*256;
        int r = idx >> 4, seg = (idx & 15)*8;
        cpa16(Axh + r*QKS + seg, Agh + (size_t)r*H + seg);
        cpa16(Axl + r*QKS + seg, Agl + (size_t)r*H + seg);
        cpa16(Bh + r*QKS + seg, Bgh + (size_t)r*H + seg);
        cpa16(Bl + r*QKS + seg, Bgl + (size_t)r*H + seg);
    }
    cp_commit(); cp_wait0();
    __syncthreads();

    int w = tid >> 5, lane = tid & 31, gid = lane >> 2, tig = lane & 3;
    int wm = (w & 3)*32, wn = (w >> 2)*64;
    float acc[2][8][4];

    auto run_gemm = [&]() {
        #pragma unroll
        for (int i = 0; i < 2; ++i)
            #pragma unroll
            for (int j = 0; j < 8; ++j)
                #pragma unroll
                for (int e = 0; e < 4; ++e) acc[i][j][e] = 0.f;
        const unsigned* A_h = (const unsigned*)Axh;
        const unsigned* A_l = (const unsigned*)Axl;
        const unsigned* B_h = (const unsigned*)Bh;
        const unsigned* B_l = (const unsigned*)Bl;
        #pragma unroll
        for (int kk = 0; kk < 8; ++kk) {
            int base = kk*8;
            unsigned ah[2][4], al[2][4];
            #pragma unroll
            for (int mi = 0; mi < 2; ++mi) {
                int r0 = (wm + mi*16 + gid)*(QKS/2);
                int r1 = r0 + 8*(QKS/2);
                ah[mi][0] = A_h[r0 + base + tig];     al[mi][0] = A_l[r0 + base + tig];
                ah[mi][1] = A_h[r1 + base + tig];     al[mi][1] = A_l[r1 + base + tig];
                ah[mi][2] = A_h[r0 + base + 4 + tig]; al[mi][2] = A_l[r0 + base + 4 + tig];
                ah[mi][3] = A_h[r1 + base + 4 + tig]; al[mi][3] = A_l[r1 + base + 4 + tig];
            }
            #pragma unroll
            for (int ni = 0; ni < 8; ++ni) {
                int n0 = (wn + ni*8 + gid)*(QKS/2);
                unsigned bh[2], bl[2];
                bh[0] = B_h[n0 + base + tig];     bh[1] = B_h[n0 + base + 4 + tig];
                bl[0] = B_l[n0 + base + tig];     bl[1] = B_l[n0 + base + 4 + tig];
                #pragma unroll
                for (int mi = 0; mi < 2; ++mi) {
                    mma_bf16(acc[mi][ni], ah[mi], bl);
                    mma_bf16(acc[mi][ni], al[mi], bh);
                    mma_bf16(acc[mi][ni], ah[mi], bh);
                }
            }
        }
    };

    // GEMM1: h2 = lrelu(xsh @ cq^T + cqb)
    run_gemm();
    __syncthreads();
    // write h2 split into A region; load attW split into B region
    #pragma unroll
    for (int mi = 0; mi < 2; ++mi)
        #pragma unroll
        for (int ni = 0; ni < 8; ++ni)
            #pragma unroll
            for (int e = 0; e < 4; ++e) {
                int r = wm + mi*16 + gid + ((e >= 2) ? 8 : 0);
                int c = wn + ni*8 + 2*tig + (e & 1);
                float v = lrelu_f(acc[mi][ni][e] + cqb[z*H + c]);
                __nv_bfloat16 hh, ll;
                split_bf(v, hh, ll);
                Axh[r*QKS + c] = hh;
                Axl[r*QKS + c] = ll;
            }
    const __nv_bfloat16* Wgh = awh + (size_t)kz*H*H;
    const __nv_bfloat16* Wgl = awl + (size_t)kz*H*H;
    #pragma unroll
    for (int i = 0; i < 8; ++i) {
        int idx = tid + i*256;
        int r = idx >> 4, seg = (idx & 15)*8;
        cpa16(Bh + r*QKS + seg, Wgh + (size_t)r*H + seg);
        cpa16(Bl + r*QKS + seg, Wgl + (size_t)r*H + seg);
    }
    cp_commit(); cp_wait0();
    __syncthreads();

    // GEMM2: wh2 = h2 @ attW^T
    run_gemm();
    #pragma unroll
    for (int mi = 0; mi < 2; ++mi)
        #pragma unroll
        for (int ni = 0; ni < 8; ++ni)
            #pragma unroll
            for (int e = 0; e < 4; ++e) {
                int r = wm + mi*16 + gid + ((e >= 2) ? 8 : 0);
                int c = wn + ni*8 + 2*tig + (e & 1);
                wh2[((size_t)z*Bq + mt*128 + r)*H + c] = acc[mi][ni][e];
            }
}

// ================= fused h1/vh GEMM + attention (bf16-split) =================
#define FU_GEMM_BYTES ((2*128*HS + 2*256*HS)*2*2)
#define FU_EPI_BYTES  ((128*132 + 128*132 + 8*128 + 128 + 128)*4)
#define FU_SMEM       (FU_EPI_BYTES > FU_GEMM_BYTES ? FU_EPI_BYTES : FU_GEMM_BYTES)
__global__ __launch_bounds__(512,1) void fused_attn(
    const __nv_bfloat16* __restrict__ yhg, const __nv_bfloat16* __restrict__ ylg,
    const __nv_bfloat16* __restrict__ ckh, const __nv_bfloat16* __restrict__ ckl,
    const float* __restrict__ ckb,
    const __nv_bfloat16* __restrict__ vwh, const __nv_bfloat16* __restrict__ vwl,
    const float* __restrict__ vb,  const float* __restrict__ wh2,
    const float* __restrict__ xsh, float* __restrict__ sout)
{
    extern __shared__ __align__(16) char smc[];
    float* sm = (float*)smc;
    __nv_bfloat16* Ah = (__nv_bfloat16*)smc;       // [2][128*HS]
    __nv_bfloat16* Al = Ah + 2*128*HS;
    __nv_bfloat16* Bh = Al + 2*128*HS;             // [2][256*HS]
    __nv_bfloat16* Bl = Bh + 2*256*HS;
    int mt = blockIdx.x, z = blockIdx.y;
    int tid = threadIdx.x;

    const __nv_bfloat16* Agh = yhg + ((size_t)z*BM_ + mt*128)*H;
    const __nv_bfloat16* Agl = ylg + ((size_t)z*BM_ + mt*128)*H;
    size_t wkb = (size_t)z*H*H;

    auto prefetch = [&](int kc, int buf) {
        {
            int r = tid >> 2, seg = (tid & 3)*8;
            int so = buf*128*HS + r*HS + seg;
            size_t ga = (size_t)r*H + kc*KC + seg;
            cpa16(Ah + so, Agh + ga);
            cpa16(Al + so, Agl + ga);
        }
        #pragma unroll
        for (int i = 0; i < 2; ++i) {
            int idx = tid + i*512;
            int n = idx >> 2, seg = (idx & 3)*8;
            int so = buf*256*HS + n*HS + seg;
            const __nv_bfloat16* srch, *srcl;
            if (n < 128) { srch = ckh + wkb + (size_t)n*H;        srcl = ckl + wkb + (size_t)n*H; }
            else         { srch = vwh + wkb + (size_t)(n-128)*H;  srcl = vwl + wkb + (size_t)(n-128)*H; }
            cpa16(Bh + so, srch + kc*KC + seg);
            cpa16(Bl + so, srcl + kc*KC + seg);
        }
    };

    int w = tid >> 5, lane = tid & 31, gid = lane >> 2, tig = lane & 3;
    int wm = (w & 3)*32, wn = (w >> 2)*64;
    float acc[2][8][4];
    #pragma unroll
    for (int i = 0; i < 2; ++i)
        #pragma unroll
        for (int j = 0; j < 8; ++j)
            #pragma unroll
            for (int e = 0; e < 4; ++e) acc[i][j][e] = 0.f;

    prefetch(0, 0); cp_commit();
    const int NCH = H/KC;  // 4
    for (int kc = 0; kc < NCH; ++kc) {
        if (kc+1 < NCH) { prefetch(kc+1, (kc+1)&1); cp_commit(); cp_wait1(); }
        else            { cp_wait0(); }
        __syncthreads();
        const unsigned* A_h = (const unsigned*)(Ah + (kc&1)*128*HS);
        const unsigned* A_l = (const unsigned*)(Al + (kc&1)*128*HS);
        const unsigned* B_h = (const unsigned*)(Bh + (kc&1)*256*HS);
        const unsigned* B_l = (const unsigned*)(Bl + (kc&1)*256*HS);
        #pragma unroll
        for (int kk = 0; kk < 2; ++kk) {
            int base = kk*8;
            unsigned ah[2][4], al[2][4];
            #pragma unroll
            for (int mi = 0; mi < 2; ++mi) {
                int r0 = (wm + mi*16 + gid)*20;
                int r1 = r0 + 8*20;
                ah[mi][0] = A_h[r0 + base + tig];     al[mi][0] = A_l[r0 + base + tig];
                ah[mi][1] = A_h[r1 + base + tig];     al[mi][1] = A_l[r1 + base + tig];
                ah[mi][2] = A_h[r0 + base + 4 + tig]; al[mi][2] = A_l[r0 + base + 4 + tig];
                ah[mi][3] = A_h[r1 + base + 4 + tig]; al[mi][3] = A_l[r1 + base + 4 + tig];
            }
            #pragma unroll
            for (int ni = 0; ni < 8; ++ni) {
                int n0 = (wn + ni*8 + gid)*20;
                unsigned bh[2], bl[2];
                bh[0] = B_h[n0 + base + tig];     bh[1] = B_h[n0 + base + 4 + tig];
                bl[0] = B_l[n0 + base + tig];     bl[1] = B_l[n0 + base + 4 + tig];
                #pragma unroll
                for (int mi = 0; mi < 2; ++mi) {
                    mma_bf16(acc[mi][ni], ah[mi], bl);
                    mma_bf16(acc[mi][ni], al[mi], bh);
                    mma_bf16(acc[mi][ni], ah[mi], bh);
                }
            }
        }
        __syncthreads();
    }

    float* SP  = sm;                 // [128][132]  h1 (lrelu+bias)
    float* SV  = SP + 128*132;       // [128][132]  vh (+bias)
    float* SW  = SV + 128*132;       // [8][128]    wh2 rows
    float* SSC = SW + 8*128;         // [128] scores
    float* SE  = SSC + 128;          // [128] softmax weights

    #pragma unroll
    for (int mi = 0; mi < 2; ++mi)
        #pragma unroll
        for (int ni = 0; ni < 8; ++ni)
            #pragma unroll
            for (int e = 0; e < 4; ++e) {
                int r = wm + mi*16 + gid + ((e >= 2) ? 8 : 0);
                int c = wn + ni*8 + 2*tig + (e & 1);
                float v = acc[mi][ni][e];
                if (c < 128) SP[r*132 + c] = lrelu_f(v + ckb[z*H + c]);
                else         SV[r*132 + (c-128)] = v + vb[z*H + (c-128)];
            }
    #pragma unroll
    for (int t = 0; t < 2; ++t) {
        int idx = tid + t*512;
        int bl = idx >> 7, o = idx & 127;
        SW[idx] = wh2[((size_t)z*Bq + mt*8 + bl)*H + o];
    }
    __syncthreads();

    #pragma unroll
    for (int i = 0; i < 8; ++i) {
        int rr = w*8 + i;
        const float* wrow = SW + (rr >> 4)*128;
        float p = 0.f;
        #pragma unroll
        for (int o = 0; o < 128; o += 32) p += SP[rr*132 + o + lane]*wrow[o + lane];
        #pragma unroll
        for (int d_ = 16; d_ > 0; d_ >>= 1) p += __shfl_xor_sync(0xffffffffu, p, d_);
        if (lane == 0) SSC[rr] = p;
    }
    __syncthreads();
    if (tid < 8) {
        float mx = -1e30f;
        #pragma unroll
        for (int m = 0; m < M; ++m) mx = fmaxf(mx, SSC[tid*M + m]);
        float es[M], sum = 0.f;
        #pragma unroll
        for (int m = 0; m < M; ++m) { es[m] = expf(SSC[tid*M + m] - mx); sum += es[m]; }
        float inv = 1.f/sum;
        #pragma unroll
        for (int m = 0; m < M; ++m) SE[tid*M + m] = es[m]*inv;
    }
    __syncthreads();

    int s = z/HN, hh = z%HN;
    #pragma unroll
    for (int t = 0; t < 2; ++t) {
        int idx = tid + t*512;
        int bl = idx >> 7, o = idx & 127;
        float a = 0.f;
        #pragma unroll
        for (int m = 0; m < M; ++m) {
            float v = SV[(bl*M + m)*132 + o]*SE[bl*M + m];
            a += (v >= 0.f) ? v : ALPHA*v;
        }
        int b = mt*8 + bl;
        sout[((size_t)s*Bq + b)*D + hh*H + o] =
            0.5f*(xsh[((size_t)z*Bq + b)*H + o] + a);
    }
}

// ---------------- semantic attention ----------------
template<int P>
__global__ __launch_bounds__(128) void semantic(
    const float* __restrict__ zin, const float* __restrict__ p1w,
    const float* __restrict__ p1b, const float* __restrict__ p2w,
    float* __restrict__ outp, int in_pstride, int in_bstride, int out_bstride)
{
    int b0 = blockIdx.x*4, tid = threadIdx.x;
    __shared__ float zs[4][P][D];
    int tot = 4*P*D;
    for (int idx = tid; idx < tot; idx += 128) {
        int d = idx % D; int rp = idx / D; int p = rp % P; int bl = rp / P;
        zs[bl][p][d] = zin[(size_t)(b0+bl)*in_bstride + (size_t)p*in_pstride + d];
    }
    __syncthreads();
    float acc[4][P];
    #pragma unroll
    for (int bl = 0; bl < 4; ++bl)
        #pragma unroll
        for (int p = 0; p < P; ++p) acc[bl][p] = 0.f;
    const float* wrow = p1w + (size_t)tid*D;
    for (int d = 0; d < D; ++d) {
        float wv = wrow[d];
        #pragma unroll
        for (int bl = 0; bl < 4; ++bl)
            #pragma unroll
            for (int p = 0; p < P; ++p) acc[bl][p] += wv*zs[bl][p][d];
    }
    float bias = p1b[tid], p2 = p2w[tid];
    __shared__ float sred[4*P][132];
    __shared__ float ssc[4*P];
    #pragma unroll
    for (int bl = 0; bl < 4; ++bl)
        #pragma unroll
        for (int p = 0; p < P; ++p)
            sred[bl*P+p][tid] = tanhf(acc[bl][p] + bias)*p2;
    __syncthreads();
    if (tid < 4*P) {
        float s_ = 0.f;
        for (int o = 0; o < H; ++o) s_ += sred[tid][o];
        ssc[tid] = s_;
    }
    __syncthreads();
    #pragma unroll
    for (int bl = 0; bl < 4; ++bl) {
        float mx = -1e30f;
        #pragma unroll
        for (int p = 0; p < P; ++p) mx = fmaxf(mx, ssc[bl*P+p]);
        float e[P]; float esum = 0.f;
        #pragma unroll
        for (int p = 0; p < P; ++p) { e[p] = expf(ssc[bl*P+p] - mx); esum += e[p]; }
        float inv = 1.f/esum;
        for (int d = tid; d < D; d += 128) {
            float o_ = 0.f;
            #pragma unroll
            for (int p = 0; p < P; ++p) o_ += e[p]*zs[bl][p][d];
            outp[(size_t)(b0+bl)*out_bstride + d] = o_*inv;
        }
    }
}

extern "C" void kernel_launch(void* const* d_in, const int* in_sizes, int n_in,
                              void* d_out, int out_size)
{
    const float* x     = (const float*)d_in[0];
    const int*   tgt   = (const int*)  d_in[1];
    const int*   neigh = (const int*)  d_in[2];
    const float* fc_w  = (const float*)d_in[3];
    const float* fc_b  = (const float*)d_in[4];
    const float* q_w   = (const float*)d_in[5];
    const float* q_b   = (const float*)d_in[6];
    const float* k_w   = (const float*)d_in[7];
    const float* k_b   = (const float*)d_in[8];
    const float* v_w   = (const float*)d_in[9];
    const float* v_b   = (const float*)d_in[10];
    const float* att_W = (const float*)d_in[11];
    const float* a1w   = (const float*)d_in[12];
    const float* a1b   = (const float*)d_in[13];
    const float* a2w   = (const float*)d_in[14];
    const float* a2b   = (const float*)d_in[15];
    const float* ip1w  = (const float*)d_in[16];
    const float* ip1b  = (const float*)d_in[17];
    const float* ip2w  = (const float*)d_in[18];
    const float* bp1w  = (const float*)d_in[19];
    const float* bp1b  = (const float*)d_in[20];
    const float* bp2w  = (const float*)d_in[21];
    float* out = (float*)d_out;

    __nv_bfloat16 *xhi,*xlo,*fwh,*fwl,*vwh,*vwl,*awh,*awl,*ckwh,*ckwl,*cqwh,*cqwl,*yh,*yl,*xshh,*xshl;
    float *ckb,*cqb,*xsh,*wh2,*sout,*mp;
    cudaGetSymbolAddress((void**)&xhi,  g_xhi);
    cudaGetSymbolAddress((void**)&xlo,  g_xlo);
    cudaGetSymbolAddress((void**)&fwh,  g_fwh);
    cudaGetSymbolAddress((void**)&fwl,  g_fwl);
    cudaGetSymbolAddress((void**)&vwh,  g_vwh);
    cudaGetSymbolAddress((void**)&vwl,  g_vwl);
    cudaGetSymbolAddress((void**)&awh,  g_awh);
    cudaGetSymbolAddress((void**)&awl,  g_awl);
    cudaGetSymbolAddress((void**)&ckwh, g_ckwh);
    cudaGetSymbolAddress((void**)&ckwl, g_ckwl);
    cudaGetSymbolAddress((void**)&ckb,  g_ckb);
    cudaGetSymbolAddress((void**)&cqwh, g_cqwh);
    cudaGetSymbolAddress((void**)&cqwl, g_cqwl);
    cudaGetSymbolAddress((void**)&cqb,  g_cqb);
    cudaGetSymbolAddress((void**)&xsh,  g_xsh);
    cudaGetSymbolAddress((void**)&xshh, g_xshh);
    cudaGetSymbolAddress((void**)&xshl, g_xshl);
    cudaGetSymbolAddress((void**)&yh,   g_yh);
    cudaGetSymbolAddress((void**)&yl,   g_yl);
    cudaGetSymbolAddress((void**)&wh2,  g_wh2);
    cudaGetSymbolAddress((void**)&sout, g_sout);
    cudaGetSymbolAddress((void**)&mp,   g_mp);

    static int smem_set = 0;
    if (!smem_set) {
        cudaFuncSetAttribute(fc_bf16,    cudaFuncAttributeMaxDynamicSharedMemorySize, FC2_SMEM);
        cudaFuncSetAttribute(qk_fused,   cudaFuncAttributeMaxDynamicSharedMemorySize, QK_SMEM);
        cudaFuncSetAttribute(fused_attn, cudaFuncAttributeMaxDynamicSharedMemorySize, FU_SMEM);
        smem_set = 1;
    }

    // 0. precompute bf16 hi/lo splits
    split2<<<(NN*IN_F + 255)/256, 256>>>(x,    xhi, xlo, NN*IN_F);
    split2<<<(S*4*H*IN_F + 255)/256, 256>>>(fc_w, fwh, fwl, S*4*H*IN_F);
    split2<<<(PAIRS*H*H + 255)/256, 256>>>(v_w,  vwh, vwl, PAIRS*H*H);
    split2<<<(KM*HN*H*H + 255)/256, 256>>>(att_W, awh, awl, KM*HN*H*H);

    // 1. fold attention-layer weights into k/q projections (tiled GEMM, split out)
    combine_gemm<<<dim3(4, PAIRS), 256>>>(a1w, a1b, k_w, k_b, ckwh, ckwl, ckb);
    combine_gemm<<<dim3(4, PAIRS), 256>>>(a2w, a2b, q_w, q_b, cqwh, cqwl, cqb);

    // 2. shared fc + leakyrelu on gathered neighbors + targets (bf16-split TC)
    fc_bf16<<<dim3(R_/128, 4, S), 256, FC2_SMEM>>>(xhi, xlo, neigh, tgt, fwh, fwl,
                                                   fc_b, yh, yl, xsh, xshh, xshl);

    // 3. wh2 = (lrelu(xsh@cq^T + cqb)) @ attW^T — fused, tensor cores
    qk_fused<<<dim3(Bq/128, PAIRS), 256, QK_SMEM>>>(xshh, xshl, cqwh, cqwl, cqb,
                                                    awh, awl, wh2);

    // 4. fused h1/vh GEMM + neighbor attention + residual (bf16-split TC)
    fused_attn<<<dim3(BM_/128, PAIRS), 512, FU_SMEM>>>(yh, yl, ckwh, ckwl, ckb,
                                                       vwh, vwl, v_b, wh2, xsh, sout);

    // 5. semantic attention within each metapath
    semantic<2><<<Bq/4, 128>>>(sout,          ip1w,       ip1b,     ip2w,     mp,     Bq*D, D, KM*D);
    semantic<3><<<Bq/4, 128>>>(sout + 2*Bq*D, ip1w + H*D, ip1b + H, ip2w + H, mp + D, Bq*D, D, KM*D);

    // 6. semantic attention between metapaths -> final output
    semantic<2><<<Bq/4, 128>>>(mp, bp1w, bp1b, bp2w, out, D, KM*D, D);
}

// round 6
// speedup vs baseline: 2.3111x; 1.0135x over previous
#include <cuda_runtime.h>
#include <cuda_bf16.h>
#include <math.h>

#define NN    20000
#define IN_F  256
#define H     128
#define HN    4
#define S     5
#define KM    2
#define Bq    1024
#define M     16
#define D     512
#define ALPHA 0.2f
#define BM_   (Bq*M)      /* 16384 */
#define R_    (BM_ + Bq)  /* 17408 */
#define PAIRS (S*HN)      /* 20 */

#define KC    32          /* K halves per pipeline stage */
#define HS    40          /* smem row stride in halves (KC + 8 pad) */

__constant__ int c_kofs[S] = {0,0,1,1,1};

// ---------------- scratch ----------------
__device__ __nv_bfloat16 g_xhi[NN*IN_F];
__device__ __nv_bfloat16 g_xlo[NN*IN_F];
__device__ __nv_bfloat16 g_fwh[S*4*H*IN_F];
__device__ __nv_bfloat16 g_fwl[S*4*H*IN_F];
__device__ __nv_bfloat16 g_vwh[PAIRS*H*H];
__device__ __nv_bfloat16 g_vwl[PAIRS*H*H];
__device__ __nv_bfloat16 g_awh[KM*HN*H*H];
__device__ __nv_bfloat16 g_awl[KM*HN*H*H];
__device__ __nv_bfloat16 g_ckwh[PAIRS*H*H];
__device__ __nv_bfloat16 g_ckwl[PAIRS*H*H];
__device__ float g_ckb[PAIRS*H];
__device__ __nv_bfloat16 g_cqwh[PAIRS*H*H];
__device__ __nv_bfloat16 g_cqwl[PAIRS*H*H];
__device__ float g_cqb[PAIRS*H];
__device__ float g_xsh[PAIRS*Bq*H];
__device__ __nv_bfloat16 g_xshh[PAIRS*Bq*H];
__device__ __nv_bfloat16 g_xshl[PAIRS*Bq*H];
__device__ __nv_bfloat16 g_yh[(size_t)PAIRS*BM_*H];
__device__ __nv_bfloat16 g_yl[(size_t)PAIRS*BM_*H];
__device__ float g_wh2[PAIRS*Bq*H];
__device__ float g_sout[S*Bq*D];
__device__ float g_mp[Bq*KM*D];

// ---------------- helpers ----------------
__device__ __forceinline__ void mma_bf16(float* d, const unsigned* a, const unsigned* b) {
    asm volatile(
      "mma.sync.aligned.m16n8k16.row.col.f32.bf16.bf16.f32 "
      "{%0,%1,%2,%3}, {%4,%5,%6,%7}, {%8,%9}, {%0,%1,%2,%3};\n"
      : "+f"(d[0]), "+f"(d[1]), "+f"(d[2]), "+f"(d[3])
      : "r"(a[0]), "r"(a[1]), "r"(a[2]), "r"(a[3]), "r"(b[0]), "r"(b[1]));
}
__device__ __forceinline__ void ldsm4(unsigned& r0, unsigned& r1, unsigned& r2, unsigned& r3,
                                      unsigned addr) {
    asm volatile("ldmatrix.sync.aligned.m8n8.x4.shared.b16 {%0,%1,%2,%3}, [%4];\n"
      : "=r"(r0), "=r"(r1), "=r"(r2), "=r"(r3) : "r"(addr));
}
__device__ __forceinline__ unsigned s2u(const void* p) {
    return (unsigned)__cvta_generic_to_shared(p);
}
__device__ __forceinline__ void split_bf(float x, __nv_bfloat16& h, __nv_bfloat16& l) {
    h = __float2bfloat16_rn(x);
    l = __float2bfloat16_rn(x - __bfloat162float(h));
}
__device__ __forceinline__ void cpa16(void* dst, const void* src) {
    unsigned d = (unsigned)__cvta_generic_to_shared(dst);
    asm volatile("cp.async.cg.shared.global [%0], [%1], 16;\n" :: "r"(d), "l"(src));
}
__device__ __forceinline__ void cp_commit() { asm volatile("cp.async.commit_group;\n"); }
__device__ __forceinline__ void cp_wait1() { asm volatile("cp.async.wait_group 1;\n"); }
__device__ __forceinline__ void cp_wait0() { asm volatile("cp.async.wait_group 0;\n"); }
__device__ __forceinline__ float lrelu_f(float v) { return v >= 0.f ? v : ALPHA*v; }

// ---------------- generic fp32 -> bf16 hi/lo split ----------------
__global__ void split2(const float* __restrict__ in, __nv_bfloat16* __restrict__ hi,
                       __nv_bfloat16* __restrict__ lo, int n)
{
    int i = blockIdx.x*256 + threadIdx.x;
    if (i < n) split_bf(in[i], hi[i], lo[i]);
}

// ---------------- combined weights: cw[o,i] = sum_j a[kz][o,j] w[z][j,i] ----------------
__global__ __launch_bounds__(256) void combine_gemm(
    const float* __restrict__ aw, const float* __restrict__ ab,
    const float* __restrict__ w,  const float* __restrict__ wb,
    __nv_bfloat16* __restrict__ cwh, __nv_bfloat16* __restrict__ cwl,
    float* __restrict__ cb)
{
    int ot = blockIdx.x, z = blockIdx.y, tid = threadIdx.x;
    int kz = c_kofs[z/HN]*HN + (z % HN);
    const float* A = aw + ((size_t)kz*H + ot*32)*H;   // [32][128]
    const float* W = w + (size_t)z*H*H;               // [128][128]
    __shared__ float sa[32][36];
    __shared__ float sw[32][132];
    int tx = tid & 15, ty = tid >> 4;                 // 16x16
    float acc[2][8];
    #pragma unroll
    for (int r = 0; r < 2; ++r)
        #pragma unroll
        for (int c = 0; c < 8; ++c) acc[r][c] = 0.f;
    for (int kc = 0; kc < 4; ++kc) {
        {
            int r = tid >> 3, c4 = (tid & 7)*4;
            *(float4*)&sa[r][c4] = *(const float4*)(A + r*H + kc*32 + c4);
        }
        #pragma unroll
        for (int i = 0; i < 4; ++i) {
            int idx = tid + i*256;
            int r = idx >> 5, c4 = (idx & 31)*4;
            *(float4*)&sw[r][c4] = *(const float4*)(W + (kc*32 + r)*H + c4);
        }
        __syncthreads();
        #pragma unroll 8
        for (int j = 0; j < 32; ++j) {
            float a0 = sa[ty*2][j], a1 = sa[ty*2+1][j];
            #pragma unroll
            for (int c = 0; c < 8; ++c) {
                float wv = sw[j][tx*8 + c];
                acc[0][c] += a0*wv;
                acc[1][c] += a1*wv;
            }
        }
        __syncthreads();
    }
    #pragma unroll
    for (int r = 0; r < 2; ++r)
        #pragma unroll
        for (int c = 0; c < 8; ++c) {
            size_t idx = ((size_t)z*H + ot*32 + ty*2 + r)*H + tx*8 + c;
            split_bf(acc[r][c], cwh[idx], cwl[idx]);
        }
    if (tid < 32) {
        int o = ot*32 + tid;
        float bacc = ab[kz*H + o];
        const float* arow = aw + ((size_t)kz*H + o)*H;
        const float* brow = wb + z*H;
        for (int j = 0; j < H; ++j) bacc += arow[j]*brow[j];
        cb[z*H + o] = bacc;
    }
}

// ================= fc GEMM (bf16-split TC, ldmatrix, gather) =================
#define FC2_SMEM (8*128*HS*2 + 512)
__global__ __launch_bounds__(256,2) void fc_bf16(
    const __nv_bfloat16* __restrict__ xh, const __nv_bfloat16* __restrict__ xl,
    const int* __restrict__ neigh, const int* __restrict__ tgt,
    const __nv_bfloat16* __restrict__ fwh, const __nv_bfloat16* __restrict__ fwl,
    const float* __restrict__ fcb,
    __nv_bfloat16* __restrict__ yh, __nv_bfloat16* __restrict__ yl,
    float* __restrict__ xsh,
    __nv_bfloat16* __restrict__ xshh, __nv_bfloat16* __restrict__ xshl)
{
    extern __shared__ __align__(16) char smc[];
    __nv_bfloat16* Ah = (__nv_bfloat16*)smc;       // [2][128*HS]
    __nv_bfloat16* Al = Ah + 2*128*HS;
    __nv_bfloat16* Bh = Al + 2*128*HS;
    __nv_bfloat16* Bl = Bh + 2*128*HS;
    int* rows = (int*)(Bl + 2*128*HS);
    int mt = blockIdx.x, nt = blockIdx.y, s = blockIdx.z;
    int tid = threadIdx.x;
    if (tid < 128) {
        int r = mt*128 + tid;
        rows[tid] = (r < BM_) ? neigh[s*BM_ + r] : tgt[r - BM_];
    }
    __syncthreads();
    size_t wb = ((size_t)s*512 + nt*128)*IN_F;

    auto prefetch = [&](int kc, int buf) {
        #pragma unroll
        for (int i = 0; i < 2; ++i) {
            int idx = tid + i*256;
            int r = idx >> 2, seg = (idx & 3)*8;
            int so = buf*128*HS + r*HS + seg;
            size_t ga = (size_t)rows[r]*IN_F + kc*KC + seg;
            size_t gb = wb + (size_t)r*IN_F + kc*KC + seg;
            cpa16(Ah + so, xh + ga);
            cpa16(Al + so, xl + ga);
            cpa16(Bh + so, fwh + gb);
            cpa16(Bl + so, fwl + gb);
        }
    };

    int w = tid >> 5, lane = tid & 31;
    int wm = (w & 3)*32, wn = (w >> 2)*64;
    // ldmatrix per-lane offsets
    int arow = lane & 15, acol = (lane & 16) ? 8 : 0;
    int bn = (lane & 7) + ((lane & 16) ? 8 : 0), bk = (lane & 8) ? 8 : 0;
    unsigned aAh = s2u(Ah), aAl = s2u(Al), aBh = s2u(Bh), aBl = s2u(Bl);

    float acc[2][8][4];
    #pragma unroll
    for (int i = 0; i < 2; ++i)
        #pragma unroll
        for (int j = 0; j < 8; ++j)
            #pragma unroll
            for (int e = 0; e < 4; ++e) acc[i][j][e] = 0.f;

    prefetch(0, 0); cp_commit();
    const int NCH = IN_F/KC;  // 8
    for (int kc = 0; kc < NCH; ++kc) {
        if (kc+1 < NCH) { prefetch(kc+1, (kc+1)&1); cp_commit(); cp_wait1(); }
        else            { cp_wait0(); }
        __syncthreads();
        unsigned bufo = (unsigned)((kc&1)*128*HS*2);
        #pragma unroll
        for (int kk = 0; kk < 2; ++kk) {
            int kb = kk*16;
            unsigned ah[2][4], al[2][4];
            #pragma unroll
            for (int mi = 0; mi < 2; ++mi) {
                unsigned off = bufo + (unsigned)(((wm + mi*16 + arow)*HS + kb + acol)*2);
                ldsm4(ah[mi][0], ah[mi][1], ah[mi][2], ah[mi][3], aAh + off);
                ldsm4(al[mi][0], al[mi][1], al[mi][2], al[mi][3], aAl + off);
            }
            unsigned bh[8][2], bl[8][2];
            #pragma unroll
            for (int nj = 0; nj < 4; ++nj) {
                unsigned off = bufo + (unsigned)(((wn + nj*16 + bn)*HS + kb + bk)*2);
                ldsm4(bh[nj*2][0], bh[nj*2][1], bh[nj*2+1][0], bh[nj*2+1][1], aBh + off);
                ldsm4(bl[nj*2][0], bl[nj*2][1], bl[nj*2+1][0], bl[nj*2+1][1], aBl + off);
            }
            #pragma unroll
            for (int ni = 0; ni < 8; ++ni)
                #pragma unroll
                for (int mi = 0; mi < 2; ++mi) {
                    mma_bf16(acc[mi][ni], ah[mi], bl[ni]);
                    mma_bf16(acc[mi][ni], al[mi], bh[ni]);
                    mma_bf16(acc[mi][ni], ah[mi], bh[ni]);
                }
        }
        __syncthreads();
    }

    int zp = s*HN + nt;
    int gid = lane >> 2, tig = lane & 3;
    float* Cs = (float*)smc;  // 128x132
    #pragma unroll
    for (int mi = 0; mi < 2; ++mi)
        #pragma unroll
        for (int ni = 0; ni < 8; ++ni)
            #pragma unroll
            for (int e = 0; e < 4; ++e) {
                int r = wm + mi*16 + gid + ((e >= 2) ? 8 : 0);
                int c = wn + ni*8 + 2*tig + (e & 1);
                Cs[r*132 + c] = lrelu_f(acc[mi][ni][e] + fcb[zp*H + c]);
            }
    __syncthreads();
    #pragma unroll
    for (int t = 0; t < 16; ++t) {
        int idx = tid + t*256;
        int rr = idx >> 5, c4 = (idx & 31)*4;
        float4 v = *(const float4*)(Cs + rr*132 + c4);
        int gr = mt*128 + rr;
        __nv_bfloat16 h0,h1,h2_,h3,l0,l1,l2,l3;
        split_bf(v.x,h0,l0); split_bf(v.y,h1,l1);
        split_bf(v.z,h2_,l2); split_bf(v.w,h3,l3);
        __nv_bfloat162 ph0 = {h0,h1}, ph1 = {h2_,h3};
        __nv_bfloat162 pl0 = {l0,l1}, pl1 = {l2,l3};
        uint2 uh, ul;
        uh.x = *(unsigned*)&ph0; uh.y = *(unsigned*)&ph1;
        ul.x = *(unsigned*)&pl0; ul.y = *(unsigned*)&pl1;
        if (gr < BM_) {
            size_t base = ((size_t)zp*BM_ + gr)*H + c4;
            *(uint2*)(yh + base) = uh;
            *(uint2*)(yl + base) = ul;
        } else {
            size_t base = ((size_t)zp*Bq + (gr - BM_))*H + c4;
            *(float4*)(xsh + base) = v;
            *(uint2*)(xshh + base) = uh;
            *(uint2*)(xshl + base) = ul;
        }
    }
}

// ================= qk_fused: wh2 = (lrelu(xsh@cq^T+cqb)) @ attW^T =================
#define QKS   136
#define QK_SMEM (4*128*QKS*2)
__global__ __launch_bounds__(256,1) void qk_fused(
    const __nv_bfloat16* __restrict__ xshh, const __nv_bfloat16* __restrict__ xshl,
    const __nv_bfloat16* __restrict__ cqh, const __nv_bfloat16* __restrict__ cql,
    const float* __restrict__ cqb,
    const __nv_bfloat16* __restrict__ awh, const __nv_bfloat16* __restrict__ awl,
    float* __restrict__ wh2)
{
    extern __shared__ __align__(16) char smc[];
    __nv_bfloat16* Axh = (__nv_bfloat16*)smc;   // [128*QKS]
    __nv_bfloat16* Axl = Axh + 128*QKS;
    __nv_bfloat16* Bh  = Axl + 128*QKS;
    __nv_bfloat16* Bl  = Bh + 128*QKS;
    int mt = blockIdx.x, z = blockIdx.y;
    int tid = threadIdx.x;
    int kz = c_kofs[z/HN]*HN + (z % HN);

    const __nv_bfloat16* Agh = xshh + ((size_t)z*Bq + mt*128)*H;
    const __nv_bfloat16* Agl = xshl + ((size_t)z*Bq + mt*128)*H;
    const __nv_bfloat16* Bgh = cqh + (size_t)z*H*H;
    const __nv_bfloat16* Bgl = cql + (size_t)z*H*H;

    #pragma unroll
    for (int i = 0; i < 8; ++i) {
        int idx = tid + i*256;
        int r = idx >> 4, seg = (idx & 15)*8;
        cpa16(Axh + r*QKS + seg, Agh + (size_t)r*H + seg);
        cpa16(Axl + r*QKS + seg, Agl + (size_t)r*H + seg);
        cpa16(Bh + r*QKS + seg, Bgh + (size_t)r*H + seg);
        cpa16(Bl + r*QKS + seg, Bgl + (size_t)r*H + seg);
    }
    cp_commit(); cp_wait0();
    __syncthreads();

    int w = tid >> 5, lane = tid & 31, gid = lane >> 2, tig = lane & 3;
    int wm = (w & 3)*32, wn = (w >> 2)*64;
    int arow = lane & 15, acol = (lane & 16) ? 8 : 0;
    int bn = (lane & 7) + ((lane & 16) ? 8 : 0), bk = (lane & 8) ? 8 : 0;
    unsigned aAh = s2u(Axh), aAl = s2u(Axl), aBh = s2u(Bh), aBl = s2u(Bl);
    float acc[2][8][4];

    auto run_gemm = [&]() {
        #pragma unroll
        for (int i = 0; i < 2; ++i)
            #pragma unroll
            for (int j = 0; j < 8; ++j)
                #pragma unroll
                for (int e = 0; e < 4; ++e) acc[i][j][e] = 0.f;
        #pragma unroll
        for (int kk = 0; kk < 8; ++kk) {
            int kb = kk*16;
            unsigned ah[2][4], al[2][4];
            #pragma unroll
            for (int mi = 0; mi < 2; ++mi) {
                unsigned off = (unsigned)(((wm + mi*16 + arow)*QKS + kb + acol)*2);
                ldsm4(ah[mi][0], ah[mi][1], ah[mi][2], ah[mi][3], aAh + off);
                ldsm4(al[mi][0], al[mi][1], al[mi][2], al[mi][3], aAl + off);
            }
            unsigned bh[8][2], bl[8][2];
            #pragma unroll
            for (int nj = 0; nj < 4; ++nj) {
                unsigned off = (unsigned)(((wn + nj*16 + bn)*QKS + kb + bk)*2);
                ldsm4(bh[nj*2][0], bh[nj*2][1], bh[nj*2+1][0], bh[nj*2+1][1], aBh + off);
                ldsm4(bl[nj*2][0], bl[nj*2][1], bl[nj*2+1][0], bl[nj*2+1][1], aBl + off);
            }
            #pragma unroll
            for (int ni = 0; ni < 8; ++ni)
                #pragma unroll
                for (int mi = 0; mi < 2; ++mi) {
                    mma_bf16(acc[mi][ni], ah[mi], bl[ni]);
                    mma_bf16(acc[mi][ni], al[mi], bh[ni]);
                    mma_bf16(acc[mi][ni], ah[mi], bh[ni]);
                }
        }
    };

    // GEMM1: h2 = lrelu(xsh @ cq^T + cqb)
    run_gemm();
    __syncthreads();
    #pragma unroll
    for (int mi = 0; mi < 2; ++mi)
        #pragma unroll
        for (int ni = 0; ni < 8; ++ni)
            #pragma unroll
            for (int e = 0; e < 4; ++e) {
                int r = wm + mi*16 + gid + ((e >= 2) ? 8 : 0);
                int c = wn + ni*8 + 2*tig + (e & 1);
                float v = lrelu_f(acc[mi][ni][e] + cqb[z*H + c]);
                __nv_bfloat16 hh, ll;
                split_bf(v, hh, ll);
                Axh[r*QKS + c] = hh;
                Axl[r*QKS + c] = ll;
            }
    const __nv_bfloat16* Wgh = awh + (size_t)kz*H*H;
    const __nv_bfloat16* Wgl = awl + (size_t)kz*H*H;
    #pragma unroll
    for (int i = 0; i < 8; ++i) {
        int idx = tid + i*256;
        int r = idx >> 4, seg = (idx & 15)*8;
        cpa16(Bh + r*QKS + seg, Wgh + (size_t)r*H + seg);
        cpa16(Bl + r*QKS + seg, Wgl + (size_t)r*H + seg);
    }
    cp_commit(); cp_wait0();
    __syncthreads();

    // GEMM2: wh2 = h2 @ attW^T
    run_gemm();
    #pragma unroll
    for (int mi = 0; mi < 2; ++mi)
        #pragma unroll
        for (int ni = 0; ni < 8; ++ni)
            #pragma unroll
            for (int e = 0; e < 4; ++e) {
                int r = wm + mi*16 + gid + ((e >= 2) ? 8 : 0);
                int c = wn + ni*8 + 2*tig + (e & 1);
                wh2[((size_t)z*Bq + mt*128 + r)*H + c] = acc[mi][ni][e];
            }
}

// ================= fused h1/vh GEMM + attention (bf16-split, ldmatrix) =================
#define FU_GEMM_BYTES ((2*128*HS + 2*256*HS)*2*2)
#define FU_EPI_BYTES  ((128*132 + 128*132 + 8*128 + 128 + 128)*4)
#define FU_SMEM       (FU_EPI_BYTES > FU_GEMM_BYTES ? FU_EPI_BYTES : FU_GEMM_BYTES)
__global__ __launch_bounds__(512,1) void fused_attn(
    const __nv_bfloat16* __restrict__ yhg, const __nv_bfloat16* __restrict__ ylg,
    const __nv_bfloat16* __restrict__ ckh, const __nv_bfloat16* __restrict__ ckl,
    const float* __restrict__ ckb,
    const __nv_bfloat16* __restrict__ vwh, const __nv_bfloat16* __restrict__ vwl,
    const float* __restrict__ vb,  const float* __restrict__ wh2,
    const float* __restrict__ xsh, float* __restrict__ sout)
{
    extern __shared__ __align__(16) char smc[];
    float* sm = (float*)smc;
    __nv_bfloat16* Ah = (__nv_bfloat16*)smc;       // [2][128*HS]
    __nv_bfloat16* Al = Ah + 2*128*HS;
    __nv_bfloat16* Bh = Al + 2*128*HS;             // [2][256*HS]
    __nv_bfloat16* Bl = Bh + 2*256*HS;
    int mt = blockIdx.x, z = blockIdx.y;
    int tid = threadIdx.x;

    const __nv_bfloat16* Agh = yhg + ((size_t)z*BM_ + mt*128)*H;
    const __nv_bfloat16* Agl = ylg + ((size_t)z*BM_ + mt*128)*H;
    size_t wkb = (size_t)z*H*H;

    auto prefetch = [&](int kc, int buf) {
        {
            int r = tid >> 2, seg = (tid & 3)*8;
            int so = buf*128*HS + r*HS + seg;
            size_t ga = (size_t)r*H + kc*KC + seg;
            cpa16(Ah + so, Agh + ga);
            cpa16(Al + so, Agl + ga);
        }
        #pragma unroll
        for (int i = 0; i < 2; ++i) {
            int idx = tid + i*512;
            int n = idx >> 2, seg = (idx & 3)*8;
            int so = buf*256*HS + n*HS + seg;
            const __nv_bfloat16* srch, *srcl;
            if (n < 128) { srch = ckh + wkb + (size_t)n*H;        srcl = ckl + wkb + (size_t)n*H; }
            else         { srch = vwh + wkb + (size_t)(n-128)*H;  srcl = vwl + wkb + (size_t)(n-128)*H; }
            cpa16(Bh + so, srch + kc*KC + seg);
            cpa16(Bl + so, srcl + kc*KC + seg);
        }
    };

    int w = tid >> 5, lane = tid & 31, gid = lane >> 2, tig = lane & 3;
    int wm = (w & 3)*32, wn = (w >> 2)*64;
    int arow = lane & 15, acol = (lane & 16) ? 8 : 0;
    int bn = (lane & 7) + ((lane & 16) ? 8 : 0), bk = (lane & 8) ? 8 : 0;
    unsigned aAh = s2u(Ah), aAl = s2u(Al), aBh = s2u(Bh), aBl = s2u(Bl);

    float acc[2][8][4];
    #pragma unroll
    for (int i = 0; i < 2; ++i)
        #pragma unroll
        for (int j = 0; j < 8; ++j)
            #pragma unroll
            for (int e = 0; e < 4; ++e) acc[i][j][e] = 0.f;

    prefetch(0, 0); cp_commit();
    const int NCH = H/KC;  // 4
    for (int kc = 0; kc < NCH; ++kc) {
        if (kc+1 < NCH) { prefetch(kc+1, (kc+1)&1); cp_commit(); cp_wait1(); }
        else            { cp_wait0(); }
        __syncthreads();
        unsigned bufA = (unsigned)((kc&1)*128*HS*2);
        unsigned bufB = (unsigned)((kc&1)*256*HS*2);
        #pragma unroll
        for (int kk = 0; kk < 2; ++kk) {
            int kb = kk*16;
            unsigned ah[2][4], al[2][4];
            #pragma unroll
            for (int mi = 0; mi < 2; ++mi) {
                unsigned off = bufA + (unsigned)(((wm + mi*16 + arow)*HS + kb + acol)*2);
                ldsm4(ah[mi][0], ah[mi][1], ah[mi][2], ah[mi][3], aAh + off);
                ldsm4(al[mi][0], al[mi][1], al[mi][2], al[mi][3], aAl + off);
            }
            unsigned bh[8][2], bl[8][2];
            #pragma unroll
            for (int nj = 0; nj < 4; ++nj) {
                unsigned off = bufB + (unsigned)(((wn + nj*16 + bn)*HS + kb + bk)*2);
                ldsm4(bh[nj*2][0], bh[nj*2][1], bh[nj*2+1][0], bh[nj*2+1][1], aBh + off);
                ldsm4(bl[nj*2][0], bl[nj*2][1], bl[nj*2+1][0], bl[nj*2+1][1], aBl + off);
            }
            #pragma unroll
            for (int ni = 0; ni < 8; ++ni)
                #pragma unroll
                for (int mi = 0; mi < 2; ++mi) {
                    mma_bf16(acc[mi][ni], ah[mi], bl[ni]);
                    mma_bf16(acc[mi][ni], al[mi], bh[ni]);
                    mma_bf16(acc[mi][ni], ah[mi], bh[ni]);
                }
        }
        __syncthreads();
    }

    float* SP  = sm;                 // [128][132]  h1 (lrelu+bias)
    float* SV  = SP + 128*132;       // [128][132]  vh (+bias)
    float* SW  = SV + 128*132;       // [8][128]    wh2 rows
    float* SSC = SW + 8*128;         // [128] scores
    float* SE  = SSC + 128;          // [128] softmax weights

    #pragma unroll
    for (int mi = 0; mi < 2; ++mi)
        #pragma unroll
        for (int ni = 0; ni < 8; ++ni)
            #pragma unroll
            for (int e = 0; e < 4; ++e) {
                int r = wm + mi*16 + gid + ((e >= 2) ? 8 : 0);
                int c = wn + ni*8 + 2*tig + (e & 1);
                float v = acc[mi][ni][e];
                if (c < 128) SP[r*132 + c] = lrelu_f(v + ckb[z*H + c]);
                else         SV[r*132 + (c-128)] = v + vb[z*H + (c-128)];
            }
    #pragma unroll
    for (int t = 0; t < 2; ++t) {
        int idx = tid + t*512;
        int bl = idx >> 7, o = idx & 127;
        SW[idx] = wh2[((size_t)z*Bq + mt*8 + bl)*H + o];
    }
    __syncthreads();

    #pragma unroll
    for (int i = 0; i < 8; ++i) {
        int rr = w*8 + i;
        const float* wrow = SW + (rr >> 4)*128;
        float p = 0.f;
        #pragma unroll
        for (int o = 0; o < 128; o += 32) p += SP[rr*132 + o + lane]*wrow[o + lane];
        #pragma unroll
        for (int d_ = 16; d_ > 0; d_ >>= 1) p += __shfl_xor_sync(0xffffffffu, p, d_);
        if (lane == 0) SSC[rr] = p;
    }
    __syncthreads();
    if (tid < 8) {
        float mx = -1e30f;
        #pragma unroll
        for (int m = 0; m < M; ++m) mx = fmaxf(mx, SSC[tid*M + m]);
        float es[M], sum = 0.f;
        #pragma unroll
        for (int m = 0; m < M; ++m) { es[m] = expf(SSC[tid*M + m] - mx); sum += es[m]; }
        float inv = 1.f/sum;
        #pragma unroll
        for (int m = 0; m < M; ++m) SE[tid*M + m] = es[m]*inv;
    }
    __syncthreads();

    int s = z/HN, hh = z%HN;
    #pragma unroll
    for (int t = 0; t < 2; ++t) {
        int idx = tid + t*512;
        int bl = idx >> 7, o = idx & 127;
        float a = 0.f;
        #pragma unroll
        for (int m = 0; m < M; ++m) {
            float v = SV[(bl*M + m)*132 + o]*SE[bl*M + m];
            a += (v >= 0.f) ? v : ALPHA*v;
        }
        int b = mt*8 + bl;
        sout[((size_t)s*Bq + b)*D + hh*H + o] =
            0.5f*(xsh[((size_t)z*Bq + b)*H + o] + a);
    }
}

// ---------------- semantic attention ----------------
template<int P>
__global__ __launch_bounds__(128) void semantic(
    const float* __restrict__ zin, const float* __restrict__ p1w,
    const float* __restrict__ p1b, const float* __restrict__ p2w,
    float* __restrict__ outp, int in_pstride, int in_bstride, int out_bstride)
{
    int b0 = blockIdx.x*4, tid = threadIdx.x;
    __shared__ float zs[4][P][D];
    int tot = 4*P*D;
    for (int idx = tid; idx < tot; idx += 128) {
        int d = idx % D; int rp = idx / D; int p = rp % P; int bl = rp / P;
        zs[bl][p][d] = zin[(size_t)(b0+bl)*in_bstride + (size_t)p*in_pstride + d];
    }
    __syncthreads();
    float acc[4][P];
    #pragma unroll
    for (int bl = 0; bl < 4; ++bl)
        #pragma unroll
        for (int p = 0; p < P; ++p) acc[bl][p] = 0.f;
    const float* wrow = p1w + (size_t)tid*D;
    for (int d = 0; d < D; ++d) {
        float wv = wrow[d];
        #pragma unroll
        for (int bl = 0; bl < 4; ++bl)
            #pragma unroll
            for (int p = 0; p < P; ++p) acc[bl][p] += wv*zs[bl][p][d];
    }
    float bias = p1b[tid], p2 = p2w[tid];
    __shared__ float sred[4*P][132];
    __shared__ float ssc[4*P];
    #pragma unroll
    for (int bl = 0; bl < 4; ++bl)
        #pragma unroll
        for (int p = 0; p < P; ++p)
            sred[bl*P+p][tid] = tanhf(acc[bl][p] + bias)*p2;
    __syncthreads();
    if (tid < 4*P) {
        float s_ = 0.f;
        for (int o = 0; o < H; ++o) s_ += sred[tid][o];
        ssc[tid] = s_;
    }
    __syncthreads();
    #pragma unroll
    for (int bl = 0; bl < 4; ++bl) {
        float mx = -1e30f;
        #pragma unroll
        for (int p = 0; p < P; ++p) mx = fmaxf(mx, ssc[bl*P+p]);
        float e[P]; float esum = 0.f;
        #pragma unroll
        for (int p = 0; p < P; ++p) { e[p] = expf(ssc[bl*P+p] - mx); esum += e[p]; }
        float inv = 1.f/esum;
        for (int d = tid; d < D; d += 128) {
            float o_ = 0.f;
            #pragma unroll
            for (int p = 0; p < P; ++p) o_ += e[p]*zs[bl][p][d];
            outp[(size_t)(b0+bl)*out_bstride + d] = o_*inv;
        }
    }
}

extern "C" void kernel_launch(void* const* d_in, const int* in_sizes, int n_in,
                              void* d_out, int out_size)
{
    const float* x     = (const float*)d_in[0];
    const int*   tgt   = (const int*)  d_in[1];
    const int*   neigh = (const int*)  d_in[2];
    const float* fc_w  = (const float*)d_in[3];
    const float* fc_b  = (const float*)d_in[4];
    const float* q_w   = (const float*)d_in[5];
    const float* q_b   = (const float*)d_in[6];
    const float* k_w   = (const float*)d_in[7];
    const float* k_b   = (const float*)d_in[8];
    const float* v_w   = (const float*)d_in[9];
    const float* v_b   = (const float*)d_in[10];
    const float* att_W = (const float*)d_in[11];
    const float* a1w   = (const float*)d_in[12];
    const float* a1b   = (const float*)d_in[13];
    const float* a2w   = (const float*)d_in[14];
    const float* a2b   = (const float*)d_in[15];
    const float* ip1w  = (const float*)d_in[16];
    const float* ip1b  = (const float*)d_in[17];
    const float* ip2w  = (const float*)d_in[18];
    const float* bp1w  = (const float*)d_in[19];
    const float* bp1b  = (const float*)d_in[20];
    const float* bp2w  = (const float*)d_in[21];
    float* out = (float*)d_out;

    __nv_bfloat16 *xhi,*xlo,*fwh,*fwl,*vwh,*vwl,*awh,*awl,*ckwh,*ckwl,*cqwh,*cqwl,*yh,*yl,*xshh,*xshl;
    float *ckb,*cqb,*xsh,*wh2,*sout,*mp;
    cudaGetSymbolAddress((void**)&xhi,  g_xhi);
    cudaGetSymbolAddress((void**)&xlo,  g_xlo);
    cudaGetSymbolAddress((void**)&fwh,  g_fwh);
    cudaGetSymbolAddress((void**)&fwl,  g_fwl);
    cudaGetSymbolAddress((void**)&vwh,  g_vwh);
    cudaGetSymbolAddress((void**)&vwl,  g_vwl);
    cudaGetSymbolAddress((void**)&awh,  g_awh);
    cudaGetSymbolAddress((void**)&awl,  g_awl);
    cudaGetSymbolAddress((void**)&ckwh, g_ckwh);
    cudaGetSymbolAddress((void**)&ckwl, g_ckwl);
    cudaGetSymbolAddress((void**)&ckb,  g_ckb);
    cudaGetSymbolAddress((void**)&cqwh, g_cqwh);
    cudaGetSymbolAddress((void**)&cqwl, g_cqwl);
    cudaGetSymbolAddress((void**)&cqb,  g_cqb);
    cudaGetSymbolAddress((void**)&xsh,  g_xsh);
    cudaGetSymbolAddress((void**)&xshh, g_xshh);
    cudaGetSymbolAddress((void**)&xshl, g_xshl);
    cudaGetSymbolAddress((void**)&yh,   g_yh);
    cudaGetSymbolAddress((void**)&yl,   g_yl);
    cudaGetSymbolAddress((void**)&wh2,  g_wh2);
    cudaGetSymbolAddress((void**)&sout, g_sout);
    cudaGetSymbolAddress((void**)&mp,   g_mp);

    static int smem_set = 0;
    if (!smem_set) {
        cudaFuncSetAttribute(fc_bf16,    cudaFuncAttributeMaxDynamicSharedMemorySize, FC2_SMEM);
        cudaFuncSetAttribute(qk_fused,   cudaFuncAttributeMaxDynamicSharedMemorySize, QK_SMEM);
        cudaFuncSetAttribute(fused_attn, cudaFuncAttributeMaxDynamicSharedMemorySize, FU_SMEM);
        smem_set = 1;
    }

    // 0. precompute bf16 hi/lo splits
    split2<<<(NN*IN_F + 255)/256, 256>>>(x,    xhi, xlo, NN*IN_F);
    split2<<<(S*4*H*IN_F + 255)/256, 256>>>(fc_w, fwh, fwl, S*4*H*IN_F);
    split2<<<(PAIRS*H*H + 255)/256, 256>>>(v_w,  vwh, vwl, PAIRS*H*H);
    split2<<<(KM*HN*H*H + 255)/256, 256>>>(att_W, awh, awl, KM*HN*H*H);

    // 1. fold attention-layer weights into k/q projections (tiled GEMM, split out)
    combine_gemm<<<dim3(4, PAIRS), 256>>>(a1w, a1b, k_w, k_b, ckwh, ckwl, ckb);
    combine_gemm<<<dim3(4, PAIRS), 256>>>(a2w, a2b, q_w, q_b, cqwh, cqwl, cqb);

    // 2. shared fc + leakyrelu on gathered neighbors + targets (bf16-split TC)
    fc_bf16<<<dim3(R_/128, 4, S), 256, FC2_SMEM>>>(xhi, xlo, neigh, tgt, fwh, fwl,
                                                   fc_b, yh, yl, xsh, xshh, xshl);

    // 3. wh2 = (lrelu(xsh@cq^T + cqb)) @ attW^T — fused, tensor cores
    qk_fused<<<dim3(Bq/128, PAIRS), 256, QK_SMEM>>>(xshh, xshl, cqwh, cqwl, cqb,
                                                    awh, awl, wh2);

    // 4. fused h1/vh GEMM + neighbor attention + residual (bf16-split TC)
    fused_attn<<<dim3(BM_/128, PAIRS), 512, FU_SMEM>>>(yh, yl, ckwh, ckwl, ckb,
                                                       vwh, vwl, v_b, wh2, xsh, sout);

    // 5. semantic attention within each metapath
    semantic<2><<<Bq/4, 128>>>(sout,          ip1w,       ip1b,     ip2w,     mp,     Bq*D, D, KM*D);
    semantic<3><<<Bq/4, 128>>>(sout + 2*Bq*D, ip1w + H*D, ip1b + H, ip2w + H, mp + D, Bq*D, D, KM*D);

    // 6. semantic attention between metapaths -> final output
    semantic<2><<<Bq/4, 128>>>(mp, bp1w, bp1b, bp2w, out, D, KM*D, D);
}